// round 1
// baseline (speedup 1.0000x reference)
#include <cuda_runtime.h>
#include <math.h>
#include <stdint.h>

namespace {
constexpr int H  = 256;
constexpr int I  = 128;
constexpr int R  = 32;
constexpr int B  = 16;
constexpr int T  = 48;
constexpr int H3 = 768;

constexpr long V_OFF    = 0;
constexpr long H_OFF    = V_OFF  + (long)B * H;
constexpr long DU_OFF   = H_OFF  + (long)B * H;
constexpr long TE_OFF   = DU_OFF + (long)B * H * H;
constexpr long TEE_OFF  = TE_OFF + (long)B * H;
constexpr long OUTS_OFF = TEE_OFF + (long)B * H * H;
constexpr long MODS_OFF = OUTS_OFF + (long)T * B * H;
}

// scratch (allocation-free rule: static __device__ arrays)
__device__ float g_Wx[(size_t)T * B * H3];   // precomputed LN(x @ Wx2h^T + b)
__device__ float g_Wh[2][B][H3];             // double-buffered Wh exchange
__device__ float g_pl[2][B][H];              // double-buffered plastic exchange

struct SM {
  float Ws[96 * 256];   // W_h2h slice (rows 64k..64k+64 and 512+32k..+32) ; prologue: W_x2h slice
  float Wm[32 * 256];   // W_h2mod
  float bh[H3];
  float lng[H3];
  float lnb[H3];
  float h[H];
  float v[H];
  float te[H];
  float x[I];
  float mod[R];
  float red[8];
  float sm2[2];
};

__device__ __forceinline__ float warp_sum(float v) {
#pragma unroll
  for (int o = 16; o > 0; o >>= 1) v += __shfl_xor_sync(0xffffffffu, v, o);
  return v;
}

__device__ __forceinline__ float sigm(float x) { return 1.0f / (1.0f + expf(-x)); }

__device__ __forceinline__ void cluster_sync_() {
  asm volatile("barrier.cluster.arrive.aligned;\n\tbarrier.cluster.wait.aligned;" ::: "memory");
}

__global__ void __cluster_dims__(8, 1, 1) __launch_bounds__(256, 1)
sgru_persistent(const float* __restrict__ x_in,
                const float* __restrict__ h0,
                const float* __restrict__ v0,
                const float* __restrict__ dU0,
                const float* __restrict__ te0,
                const float* __restrict__ tE0,
                const float* __restrict__ Wx2h,
                const float* __restrict__ bx2h,
                const float* __restrict__ Wh2h,
                const float* __restrict__ bh2h,
                const float* __restrict__ lnxg,
                const float* __restrict__ lnxb,
                const float* __restrict__ lnhg,
                const float* __restrict__ lnhb,
                const float* __restrict__ Wh2mod,
                const float* __restrict__ bh2mod,
                const float* __restrict__ Wmod2h,
                const float* __restrict__ bmod2h,
                const float* __restrict__ alpha,
                const float* __restrict__ tauU,
                float* __restrict__ out)
{
  extern __shared__ unsigned char smem_raw[];
  SM* S = reinterpret_cast<SM*>(smem_raw);
  const int tid  = threadIdx.x;
  const int wid  = tid >> 5;
  const int lane = tid & 31;
  const int rank = blockIdx.x & 7;   // CTA rank within cluster (owns 32 dU rows)
  const int b    = blockIdx.x >> 3;  // batch index

  const float a0    = alpha[0];
  const float sp_a  = (a0 > 0.f) ? (a0 + log1pf(expf(-a0))) : log1pf(expf(a0));
  const float inv_spa = 1.0f / sp_a;
  const float tau   = sigm(tauU[0]);

  // ---------------- prologue: Wx = LN(x @ Wx2h^T + b_x2h) for all t ------------
  // load W_x2h slice rows [96*rank, 96*rank+96) (96 x 128) into smem
  for (int i = tid; i < 96 * I; i += 256) {
    int q = i >> 7, c = i & (I - 1);
    S->Ws[i] = Wx2h[(96 * rank + q) * I + c];
  }
  __syncthreads();
  for (int t = 0; t < T; ++t) {
    if (tid < I) S->x[tid] = x_in[((size_t)t * B + b) * I + tid];
    __syncthreads();
    for (int rq = 0; rq < 12; ++rq) {
      int q = wid * 12 + rq;
      float acc = 0.f;
#pragma unroll
      for (int jj = 0; jj < 4; ++jj)
        acc += S->Ws[q * I + lane + 32 * jj] * S->x[lane + 32 * jj];
      acc = warp_sum(acc);
      if (lane == 0) {
        int o = 96 * rank + q;
        g_Wx[((size_t)t * B + b) * H3 + o] = acc + bx2h[o];
      }
    }
    __syncthreads();
  }
  cluster_sync_();
  // LayerNorm pass: CTA `rank` normalizes timesteps t = rank, rank+8, ...
  for (int t = rank; t < T; t += 8) {
    float* base = &g_Wx[((size_t)t * B + b) * H3];
    float w0 = base[tid], w1 = base[tid + 256], w2 = base[tid + 512];
    float ts = warp_sum(w0 + w1 + w2);
    __syncthreads();
    if (lane == 0) S->red[wid] = ts;
    __syncthreads();
    float mu = 0.f;
#pragma unroll
    for (int i = 0; i < 8; ++i) mu += S->red[i];
    mu *= (1.0f / H3);
    float d0 = w0 - mu, d1 = w1 - mu, d2 = w2 - mu;
    float sq = warp_sum(d0 * d0 + d1 * d1 + d2 * d2);
    __syncthreads();
    if (lane == 0) S->red[wid] = sq;
    __syncthreads();
    float var = 0.f;
#pragma unroll
    for (int i = 0; i < 8; ++i) var += S->red[i];
    float rstd = rsqrtf(var * (1.0f / H3) + 1e-5f);
    base[tid]       = d0 * rstd * lnxg[tid]       + lnxb[tid];
    base[tid + 256] = d1 * rstd * lnxg[tid + 256] + lnxb[tid + 256];
    base[tid + 512] = d2 * rstd * lnxg[tid + 512] + lnxb[tid + 512];
  }

  // ---------------- load main-loop smem + register-resident state --------------
  // W_h2h slice: rows q<64 -> 64*rank+q ; q>=64 -> 512+32*rank+(q-64)  (includes own Wv rows)
  for (int i = tid; i < 96 * H; i += 256) {
    int q = i >> 8, c = i & (H - 1);
    int o = (q < 64) ? (64 * rank + q) : (512 + 32 * rank + (q - 64));
    S->Ws[i] = Wh2h[o * H + c];
  }
  for (int i = tid; i < R * H; i += 256) S->Wm[i] = Wh2mod[i];
  for (int i = tid; i < H3; i += 256) {
    S->bh[i] = bh2h[i]; S->lng[i] = lnhg[i]; S->lnb[i] = lnhb[i];
  }
  S->h[tid]  = h0[b * H + tid];
  S->v[tid]  = v0[b * H + tid];
  S->te[tid] = te0[b * H + tid];

  // dU / trace_E rows [32*rank, 32*rank+32): warp owns 4 rows, lane owns cols lane+32j
  float dUr[4][8], tEr[4][8];
#pragma unroll
  for (int rr = 0; rr < 4; ++rr) {
    int gi = 32 * rank + wid * 4 + rr;
    size_t rb = ((size_t)b * H + gi) * H;
#pragma unroll
    for (int j = 0; j < 8; ++j) {
      dUr[rr][j] = dU0[rb + lane + 32 * j];
      tEr[rr][j] = tE0[rb + lane + 32 * j];
    }
  }
  __syncthreads();
  cluster_sync_();

  // ---------------- main scan: 1 cluster.sync per step --------------------------
  int par = 0;
  for (int t = 0; t < T; ++t, par ^= 1) {
    // phase 1: plastic rows (sp_a * dU @ h) + Wh slice rows (h @ W_h2h^T + b)
#pragma unroll
    for (int rr = 0; rr < 4; ++rr) {
      float p = 0.f;
#pragma unroll
      for (int j = 0; j < 8; ++j) p += dUr[rr][j] * S->h[lane + 32 * j];
      p = warp_sum(p);
      if (lane == 0) g_pl[par][b][32 * rank + wid * 4 + rr] = sp_a * p;
    }
    for (int rq = 0; rq < 12; ++rq) {
      int q = wid * 12 + rq;
      float acc = 0.f;
#pragma unroll
      for (int j = 0; j < 8; ++j)
        acc += S->Ws[q * H + lane + 32 * j] * S->h[lane + 32 * j];
      acc = warp_sum(acc);
      if (lane == 0) {
        int o = (q < 64) ? (64 * rank + q) : (512 + 32 * rank + (q - 64));
        g_Wh[par][b][o] = acc + S->bh[o];
      }
    }
    cluster_sync_();  // release/acquire: Wh + plastic visible cluster-wide

    // phase 2 (replicated in each cluster CTA): LN, gates, v/h/te update, mod
    const float* whb = g_Wh[par][b];
    float w0 = whb[tid];
    float w1 = whb[tid + 256];
    float w2 = whb[tid + 512] + g_pl[par][b][tid];
    float ts = warp_sum(w0 + w1 + w2);
    __syncthreads();
    if (lane == 0) S->red[wid] = ts;
    __syncthreads();
    float mu = 0.f;
#pragma unroll
    for (int i = 0; i < 8; ++i) mu += S->red[i];
    mu *= (1.0f / H3);
    float d0 = w0 - mu, d1 = w1 - mu, d2 = w2 - mu;
    float sq = warp_sum(d0 * d0 + d1 * d1 + d2 * d2);
    __syncthreads();
    if (lane == 0) S->red[wid] = sq;
    __syncthreads();
    float var = 0.f;
#pragma unroll
    for (int i = 0; i < 8; ++i) var += S->red[i];
    float rstd = rsqrtf(var * (1.0f / H3) + 1e-5f);

    const float* wx = &g_Wx[((size_t)t * B + b) * H3];
    float pre0 = d0 * rstd * S->lng[tid]       + S->lnb[tid]       + wx[tid];
    float pre1 = d1 * rstd * S->lng[tid + 256] + S->lnb[tid + 256] + wx[tid + 256];
    float pre2 = d2 * rstd * S->lng[tid + 512] + S->lnb[tid + 512] + wx[tid + 512];
    float z = sigm(pre0), r = sigm(pre1);
    float vn  = (1.f - z) * S->v[tid] + z * pre2;
    float hn  = fmaxf(vn, 0.f);
    float ten = (1.f - r) * S->te[tid] + r * S->h[tid];  // uses OLD h
    S->v[tid]  = vn;
    S->h[tid]  = hn;
    S->te[tid] = ten;
    if (rank == 0) out[OUTS_OFF + ((size_t)t * B + b) * H + tid] = hn;
    __syncthreads();

    // mod = relu(h_new @ W_h2mod^T + b)
#pragma unroll
    for (int rr = 0; rr < 4; ++rr) {
      int j = wid * 4 + rr;
      float acc = 0.f;
#pragma unroll
      for (int jj = 0; jj < 8; ++jj)
        acc += S->Wm[j * H + lane + 32 * jj] * S->h[lane + 32 * jj];
      acc = warp_sum(acc);
      if (lane == 0) S->mod[j] = fmaxf(acc + bh2mod[j], 0.f);
    }
    __syncthreads();
    if (wid == 0) {
      float mj = S->mod[lane];
      float t0 = warp_sum(Wmod2h[lane] * mj);
      float t1 = warp_sum(Wmod2h[R + lane] * mj);
      if (lane == 0) {
        S->sm2[0] = sigm(t0 + bmod2h[0]);
        S->sm2[1] = t1 + bmod2h[1];
      }
    }
    if (rank == 0 && tid < R)
      out[MODS_OFF + ((size_t)t * B + b) * R + tid] = S->mod[tid];
    __syncthreads();
    float s = S->sm2[0], m = S->sm2[1];

    // phase 3: register-resident state update (outer, tE, dU + clip)
#pragma unroll
    for (int rr = 0; rr < 4; ++rr) {
      int gi = 32 * rank + wid * 4 + rr;
      float hni  = S->h[gi];
      float teni = S->te[gi];
#pragma unroll
      for (int j = 0; j < 8; ++j) {
        int c = lane + 32 * j;
        float outer = hni * S->te[c] - teni * S->h[c];
        float E = tEr[rr][j] + s * (outer - tEr[rr][j]);
        tEr[rr][j] = E;
        float d = dUr[rr][j] + tau * (m * E - dUr[rr][j]);
        float wv = S->Ws[(64 + wid * 4 + rr) * H + c];  // own Wv rows live in slice
        float up = fmaxf(1.f - wv, 0.f) * inv_spa;
        float lo = -fmaxf(1.f + wv, 0.f) * inv_spa;
        dUr[rr][j] = fminf(fmaxf(d, lo), up);
      }
    }
    // next phase 1 only reads S->h / register state; cluster_sync at its end orders buffers
  }

  // ---------------- epilogue: final state ---------------------------------------
  if (rank == 0) {
    out[V_OFF  + b * H + tid] = S->v[tid];
    out[H_OFF  + b * H + tid] = S->h[tid];
    out[TE_OFF + b * H + tid] = S->te[tid];
  }
#pragma unroll
  for (int rr = 0; rr < 4; ++rr) {
    int gi = 32 * rank + wid * 4 + rr;
    size_t rb = ((size_t)b * H + gi) * H;
#pragma unroll
    for (int j = 0; j < 8; ++j) {
      out[DU_OFF  + rb + lane + 32 * j] = dUr[rr][j];
      out[TEE_OFF + rb + lane + 32 * j] = tEr[rr][j];
    }
  }
}

extern "C" void kernel_launch(void* const* d_in, const int* in_sizes, int n_in,
                              void* d_out, int out_size) {
  (void)in_sizes; (void)n_in; (void)out_size;
  const float* x_in   = (const float*)d_in[0];
  const float* h0     = (const float*)d_in[1];
  const float* v0     = (const float*)d_in[2];
  const float* dU0    = (const float*)d_in[3];
  const float* te0    = (const float*)d_in[4];
  const float* tE0    = (const float*)d_in[5];
  const float* Wx2h   = (const float*)d_in[6];
  const float* bx2h   = (const float*)d_in[7];
  const float* Wh2h   = (const float*)d_in[8];
  const float* bh2h   = (const float*)d_in[9];
  const float* lnxg   = (const float*)d_in[10];
  const float* lnxb   = (const float*)d_in[11];
  const float* lnhg   = (const float*)d_in[12];
  const float* lnhb   = (const float*)d_in[13];
  const float* Wh2mod = (const float*)d_in[14];
  const float* bh2mod = (const float*)d_in[15];
  const float* Wmod2h = (const float*)d_in[16];
  const float* bmod2h = (const float*)d_in[17];
  const float* alpha  = (const float*)d_in[18];
  const float* tauU   = (const float*)d_in[19];
  float* out = (float*)d_out;

  cudaFuncSetAttribute(sgru_persistent,
                       cudaFuncAttributeMaxDynamicSharedMemorySize,
                       (int)sizeof(SM));
  sgru_persistent<<<B * 8, 256, sizeof(SM)>>>(
      x_in, h0, v0, dU0, te0, tE0, Wx2h, bx2h, Wh2h, bh2h,
      lnxg, lnxb, lnhg, lnhb, Wh2mod, bh2mod, Wmod2h, bmod2h,
      alpha, tauU, out);
}

// round 2
// speedup vs baseline: 1.7840x; 1.7840x over previous
#include <cuda_runtime.h>
#include <math.h>
#include <stdint.h>

namespace {
constexpr int H  = 256;
constexpr int I  = 128;
constexpr int R  = 32;
constexpr int B  = 16;
constexpr int T  = 48;
constexpr int H3 = 768;

constexpr long V_OFF    = 0;
constexpr long H_OFF    = V_OFF  + (long)B * H;
constexpr long DU_OFF   = H_OFF  + (long)B * H;
constexpr long TE_OFF   = DU_OFF + (long)B * H * H;
constexpr long TEE_OFF  = TE_OFF + (long)B * H;
constexpr long OUTS_OFF = TEE_OFF + (long)B * H * H;
constexpr long MODS_OFF = OUTS_OFF + (long)T * B * H;
}

// one-time exchange of the x-projection (prologue only)
__device__ float g_Wx[(size_t)T * B * H3];

struct SM {
  float Ws[96 * 256];    // W_h2h slice (prologue: W_x2h slice in first 96*128)
  float Wm[32 * 256];    // W_h2mod
  float whx[2][H3];      // DSMEM-exchanged Wh (bias included), double buffered
  float plx[2][H];       // DSMEM-exchanged plastic, double buffered
  float bh[H3];
  float lng[H3];
  float lnb[H3];
  float h[H];
  float te[H];
  float mod[R];
  float reds[8];
  float redq[8];
  float wm2[2 * R];
  float bhm[R];
};

__device__ __forceinline__ float warp_bfly(float v) {
#pragma unroll
  for (int o = 16; o; o >>= 1) v += __shfl_xor_sync(0xffffffffu, v, o);
  return v;
}

__device__ __forceinline__ float sigm(float x) { return 1.0f / (1.0f + __expf(-x)); }

__device__ __forceinline__ void cluster_sync_() {
  asm volatile("barrier.cluster.arrive.aligned;\n\tbarrier.cluster.wait.aligned;" ::: "memory");
}

__device__ __forceinline__ uint32_t smem_u32(const void* p) {
  return (uint32_t)__cvta_generic_to_shared(p);
}

__device__ __forceinline__ uint32_t mapa_u32(uint32_t addr, uint32_t peer) {
  uint32_t r;
  asm("mapa.shared::cluster.u32 %0, %1, %2;" : "=r"(r) : "r"(addr), "r"(peer));
  return r;
}

__device__ __forceinline__ void st_cluster_f32(uint32_t addr, float v) {
  asm volatile("st.shared::cluster.f32 [%0], %1;" :: "r"(addr), "f"(v) : "memory");
}

__device__ __forceinline__ float dot4(float4 a, const float* h) {
  return a.x * h[0] + a.y * h[1] + a.z * h[2] + a.w * h[3];
}

__global__ void __cluster_dims__(8, 1, 1) __launch_bounds__(256, 1)
sgru_persistent(const float* __restrict__ x_in,
                const float* __restrict__ h0,
                const float* __restrict__ v0,
                const float* __restrict__ dU0,
                const float* __restrict__ te0,
                const float* __restrict__ tE0,
                const float* __restrict__ Wx2h,
                const float* __restrict__ bx2h,
                const float* __restrict__ Wh2h,
                const float* __restrict__ bh2h,
                const float* __restrict__ lnxg,
                const float* __restrict__ lnxb,
                const float* __restrict__ lnhg,
                const float* __restrict__ lnhb,
                const float* __restrict__ Wh2mod,
                const float* __restrict__ bh2mod,
                const float* __restrict__ Wmod2h,
                const float* __restrict__ bmod2h,
                const float* __restrict__ alpha,
                const float* __restrict__ tauU,
                float* __restrict__ out)
{
  extern __shared__ unsigned char smem_raw[];
  SM* S = reinterpret_cast<SM*>(smem_raw);
  const int tid  = threadIdx.x;
  const int wid  = tid >> 5;
  const int lane = tid & 31;
  const int rank = blockIdx.x & 7;   // CTA rank in cluster: owns 32 dU rows
  const int b    = blockIdx.x >> 3;  // batch index

  const float a0      = alpha[0];
  const float sp_a    = (a0 > 0.f) ? (a0 + log1pf(expf(-a0))) : log1pf(expf(a0));
  const float inv_spa = 1.0f / sp_a;
  const float tau     = sigm(tauU[0]);
  const float bm0     = bmod2h[0];
  const float bm1     = bmod2h[1];

  // ============ prologue: Wx = x @ Wx2h^T + b (raw), warp-parallel over t =====
  {
    const float4* WxA = (const float4*)(Wx2h + (size_t)96 * rank * I);
    float4* Ws4w = (float4*)S->Ws;
    for (int i = tid; i < 96 * I / 4; i += 256) Ws4w[i] = WxA[i];
  }
  __syncthreads();
  {
    const float4* Ws4 = (const float4*)S->Ws;
    for (int i = 0; i < 6; ++i) {
      int t = wid + 8 * i;
      const float4 x4 = ((const float4*)x_in)[(size_t)(t * B + b) * 32 + lane];
      float keep0 = 0.f, keep1 = 0.f, keep2 = 0.f;
#pragma unroll
      for (int g = 0; g < 3; ++g) {
#pragma unroll
        for (int qq = 0; qq < 32; ++qq) {
          int q = g * 32 + qq;
          float4 w = Ws4[q * 32 + lane];
          float acc = w.x * x4.x + w.y * x4.y + w.z * x4.z + w.w * x4.w;
          acc = warp_bfly(acc);
          if (lane == qq) { if (g == 0) keep0 = acc; else if (g == 1) keep1 = acc; else keep2 = acc; }
        }
      }
      size_t base = (size_t)(t * B + b) * H3 + 96 * rank;
      g_Wx[base + lane]      = keep0 + bx2h[96 * rank + lane];
      g_Wx[base + 32 + lane] = keep1 + bx2h[96 * rank + 32 + lane];
      g_Wx[base + 64 + lane] = keep2 + bx2h[96 * rank + 64 + lane];
    }
  }
  cluster_sync_();

  // ============ prologue LN over g_Wx: CTA `rank` handles t = rank, rank+8, ...
  for (int t = rank; t < T; t += 8) {
    float* base = &g_Wx[(size_t)(t * B + b) * H3];
    float w0 = base[tid], w1 = base[tid + 256], w2 = base[tid + 512];
    float s1 = w0 + w1 + w2;
    float s2 = w0 * w0 + w1 * w1 + w2 * w2;
#pragma unroll
    for (int o = 16; o; o >>= 1) {
      s1 += __shfl_xor_sync(0xffffffffu, s1, o);
      s2 += __shfl_xor_sync(0xffffffffu, s2, o);
    }
    if (lane == 0) { S->reds[wid] = s1; S->redq[wid] = s2; }
    __syncthreads();
    float ssum = 0.f, ssq = 0.f;
#pragma unroll
    for (int i = 0; i < 8; ++i) { ssum += S->reds[i]; ssq += S->redq[i]; }
    float mu  = ssum * (1.0f / H3);
    float var = ssq * (1.0f / H3) - mu * mu;
    float rstd = rsqrtf(var + 1e-5f);
    base[tid]       = (w0 - mu) * rstd * lnxg[tid]       + lnxb[tid];
    base[tid + 256] = (w1 - mu) * rstd * lnxg[tid + 256] + lnxb[tid + 256];
    base[tid + 512] = (w2 - mu) * rstd * lnxg[tid + 512] + lnxb[tid + 512];
    __syncthreads();
  }

  // ============ load main-loop smem + register-resident state ==================
  {
    const float4* WhA = (const float4*)(Wh2h + (size_t)64 * rank * H);
    const float4* WhB = (const float4*)(Wh2h + (size_t)(512 + 32 * rank) * H);
    const float4* Wm4 = (const float4*)Wh2mod;
    float4* Ws4w = (float4*)S->Ws;
    float4* Wm4w = (float4*)S->Wm;
    for (int i = tid; i < 64 * 64; i += 256) Ws4w[i] = WhA[i];
    for (int i = tid; i < 32 * 64; i += 256) Ws4w[64 * 64 + i] = WhB[i];
    for (int i = tid; i < 32 * 64; i += 256) Wm4w[i] = Wm4[i];
    for (int i = tid; i < H3; i += 256) {
      S->bh[i] = bh2h[i]; S->lng[i] = lnhg[i]; S->lnb[i] = lnhb[i];
    }
    for (int i = tid; i < 2 * R; i += 256) S->wm2[i] = Wmod2h[i];
    for (int i = tid; i < R; i += 256) S->bhm[i] = bh2mod[i];
  }
  float h_own  = h0[b * H + tid];
  float v_own  = v0[b * H + tid];
  float te_own = te0[b * H + tid];
  S->h[tid]  = h_own;
  S->te[tid] = te_own;

  // per-thread column ownership: cols {4*lane+k, 128+4*lane+k}, k<4
  float dUr[4][8], tEr[4][8], wvr[4][8];
#pragma unroll
  for (int rr = 0; rr < 4; ++rr) {
    int gi = 32 * rank + wid * 4 + rr;
    const float4* du4 = (const float4*)(dU0 + ((size_t)b * H + gi) * H);
    const float4* tE4 = (const float4*)(tE0 + ((size_t)b * H + gi) * H);
    const float4* wv4 = (const float4*)(Wh2h + (size_t)(512 + gi) * H);
    float4 a, c;
    a = du4[lane]; c = du4[32 + lane];
    dUr[rr][0]=a.x; dUr[rr][1]=a.y; dUr[rr][2]=a.z; dUr[rr][3]=a.w;
    dUr[rr][4]=c.x; dUr[rr][5]=c.y; dUr[rr][6]=c.z; dUr[rr][7]=c.w;
    a = tE4[lane]; c = tE4[32 + lane];
    tEr[rr][0]=a.x; tEr[rr][1]=a.y; tEr[rr][2]=a.z; tEr[rr][3]=a.w;
    tEr[rr][4]=c.x; tEr[rr][5]=c.y; tEr[rr][6]=c.z; tEr[rr][7]=c.w;
    a = wv4[lane]; c = wv4[32 + lane];
    wvr[rr][0]=a.x; wvr[rr][1]=a.y; wvr[rr][2]=a.z; wvr[rr][3]=a.w;
    wvr[rr][4]=c.x; wvr[rr][5]=c.y; wvr[rr][6]=c.z; wvr[rr][7]=c.w;
  }

  // DSMEM peer bases (lane < 8 stores to peer = lane)
  const uint32_t whx_peer = mapa_u32(smem_u32(&S->whx[0][0]), lane & 7);
  const uint32_t plx_peer = mapa_u32(smem_u32(&S->plx[0][0]), lane & 7);

  cluster_sync_();  // also CTA barrier: S->h/S->te + weights visible

  float hreg[8], tereg[8];
  {
    const float4* h4 = (const float4*)S->h;
    const float4* t4 = (const float4*)S->te;
    float4 a = h4[lane], c = h4[32 + lane];
    hreg[0]=a.x; hreg[1]=a.y; hreg[2]=a.z; hreg[3]=a.w;
    hreg[4]=c.x; hreg[5]=c.y; hreg[6]=c.z; hreg[7]=c.w;
    a = t4[lane]; c = t4[32 + lane];
    tereg[0]=a.x; tereg[1]=a.y; tereg[2]=a.z; tereg[3]=a.w;
    tereg[4]=c.x; tereg[5]=c.y; tereg[6]=c.z; tereg[7]=c.w;
  }

  const float4* Ws4 = (const float4*)S->Ws;
  const float4* Wm4 = (const float4*)S->Wm;

  // ============ main scan ========================================================
  int par = 0;
  for (int t = 0; t < T; ++t, par ^= 1) {
    // prefetch x-projection for phase 2 (hide L2 latency behind phase 1)
    const float* wxp = &g_Wx[(size_t)(t * B + b) * H3];
    float wx0 = __ldcg(wxp + tid);
    float wx1 = __ldcg(wxp + tid + 256);
    float wx2 = __ldcg(wxp + tid + 512);

    // ---- phase 1: Wh rows (12/warp) + plastic rows (4/warp), batched reduce
    float acc[16];
#pragma unroll
    for (int rq = 0; rq < 12; ++rq) {
      int q = wid * 12 + rq;
      float4 wA = Ws4[q * 64 + lane];
      float4 wB = Ws4[q * 64 + 32 + lane];
      acc[rq] = dot4(wA, hreg) + dot4(wB, hreg + 4);
    }
#pragma unroll
    for (int rr = 0; rr < 4; ++rr) {
      float p = 0.f;
#pragma unroll
      for (int j = 0; j < 8; ++j) p += dUr[rr][j] * hreg[j];
      acc[12 + rr] = p * sp_a;
    }
#pragma unroll
    for (int o = 16; o; o >>= 1)
#pragma unroll
      for (int k = 0; k < 16; ++k) acc[k] += __shfl_xor_sync(0xffffffffu, acc[k], o);

    if (lane < 8) {
      uint32_t wbase = whx_peer + (uint32_t)(par * H3) * 4u;
      uint32_t pbase = plx_peer + (uint32_t)(par * H)  * 4u;
#pragma unroll
      for (int rq = 0; rq < 12; ++rq) {
        int q = wid * 12 + rq;
        int o = (q < 64) ? (64 * rank + q) : (512 + 32 * rank + (q - 64));
        st_cluster_f32(wbase + (uint32_t)o * 4u, acc[rq] + S->bh[o]);
      }
#pragma unroll
      for (int rr = 0; rr < 4; ++rr) {
        int gi = 32 * rank + wid * 4 + rr;
        st_cluster_f32(pbase + (uint32_t)gi * 4u, acc[12 + rr]);
      }
    }
    cluster_sync_();

    // ---- phase 2 (replicated): LN + gates + state vectors
    float w0 = S->whx[par][tid];
    float w1 = S->whx[par][tid + 256];
    float w2 = S->whx[par][tid + 512] + S->plx[par][tid];
    float s1 = w0 + w1 + w2;
    float s2 = w0 * w0 + w1 * w1 + w2 * w2;
#pragma unroll
    for (int o = 16; o; o >>= 1) {
      s1 += __shfl_xor_sync(0xffffffffu, s1, o);
      s2 += __shfl_xor_sync(0xffffffffu, s2, o);
    }
    if (lane == 0) { S->reds[wid] = s1; S->redq[wid] = s2; }
    __syncthreads();                                   // (A)
    float ssum = 0.f, ssq = 0.f;
#pragma unroll
    for (int i = 0; i < 8; ++i) { ssum += S->reds[i]; ssq += S->redq[i]; }
    float mu   = ssum * (1.0f / H3);
    float var  = ssq * (1.0f / H3) - mu * mu;
    float rstd = rsqrtf(var + 1e-5f);

    float pre0 = (w0 - mu) * rstd * S->lng[tid]       + S->lnb[tid]       + wx0;
    float pre1 = (w1 - mu) * rstd * S->lng[tid + 256] + S->lnb[tid + 256] + wx1;
    float pre2 = (w2 - mu) * rstd * S->lng[tid + 512] + S->lnb[tid + 512] + wx2;
    float z  = sigm(pre0);
    float r  = sigm(pre1);
    float vn = v_own + z * (pre2 - v_own);
    float hn = fmaxf(vn, 0.f);
    float tn = te_own + r * (h_own - te_own);          // uses OLD h
    v_own = vn; h_own = hn; te_own = tn;
    S->h[tid]  = hn;
    S->te[tid] = tn;
    if (rank == 0) out[OUTS_OFF + (size_t)(t * B + b) * H + tid] = hn;
    __syncthreads();                                   // (B)

    // reload column registers (new h / te)
    {
      const float4* h4 = (const float4*)S->h;
      const float4* t4 = (const float4*)S->te;
      float4 a = h4[lane], c = h4[32 + lane];
      hreg[0]=a.x; hreg[1]=a.y; hreg[2]=a.z; hreg[3]=a.w;
      hreg[4]=c.x; hreg[5]=c.y; hreg[6]=c.z; hreg[7]=c.w;
      a = t4[lane]; c = t4[32 + lane];
      tereg[0]=a.x; tereg[1]=a.y; tereg[2]=a.z; tereg[3]=a.w;
      tereg[4]=c.x; tereg[5]=c.y; tereg[6]=c.z; tereg[7]=c.w;
    }

    // ---- mod = relu(h_new @ Wm^T + b): 4 rows per warp
    float macc[4];
#pragma unroll
    for (int rr = 0; rr < 4; ++rr) {
      int j = wid * 4 + rr;
      float4 wA = Wm4[j * 64 + lane];
      float4 wB = Wm4[j * 64 + 32 + lane];
      macc[rr] = dot4(wA, hreg) + dot4(wB, hreg + 4);
    }
#pragma unroll
    for (int o = 16; o; o >>= 1)
#pragma unroll
      for (int k = 0; k < 4; ++k) macc[k] += __shfl_xor_sync(0xffffffffu, macc[k], o);
    if (lane < 4) S->mod[wid * 4 + lane] =
        fmaxf(((lane==0)?macc[0]:(lane==1)?macc[1]:(lane==2)?macc[2]:macc[3])
              + S->bhm[wid * 4 + lane], 0.f);
    __syncthreads();                                   // (C)

    // every warp computes s, m redundantly (no extra barrier)
    float mj = S->mod[lane];
    float t0 = mj * S->wm2[lane];
    float t1 = mj * S->wm2[32 + lane];
#pragma unroll
    for (int o = 16; o; o >>= 1) {
      t0 += __shfl_xor_sync(0xffffffffu, t0, o);
      t1 += __shfl_xor_sync(0xffffffffu, t1, o);
    }
    float s = sigm(t0 + bm0);
    float m = t1 + bm1;
    if (rank == 0 && tid < R)
      out[MODS_OFF + (size_t)(t * B + b) * R + tid] = S->mod[tid];

    // ---- phase 3: register-resident dU / tE update + clip
#pragma unroll
    for (int rr = 0; rr < 4; ++rr) {
      int gi = 32 * rank + wid * 4 + rr;
      float hni  = S->h[gi];
      float teni = S->te[gi];
#pragma unroll
      for (int j = 0; j < 8; ++j) {
        float outer = hni * tereg[j] - teni * hreg[j];
        float E = tEr[rr][j] + s * (outer - tEr[rr][j]);
        tEr[rr][j] = E;
        float d  = dUr[rr][j] + tau * (m * E - dUr[rr][j]);
        float wv = wvr[rr][j];
        float up = fmaxf(1.f - wv, 0.f) * inv_spa;
        float lo = -fmaxf(1.f + wv, 0.f) * inv_spa;
        dUr[rr][j] = fminf(fmaxf(d, lo), up);
      }
    }
    // next iteration's phase 1 uses hreg/dUr (registers); cluster_sync orders buffers
  }

  // ============ epilogue =========================================================
  if (rank == 0) {
    out[V_OFF  + b * H + tid] = v_own;
    out[H_OFF  + b * H + tid] = h_own;
    out[TE_OFF + b * H + tid] = te_own;
  }
#pragma unroll
  for (int rr = 0; rr < 4; ++rr) {
    int gi = 32 * rank + wid * 4 + rr;
    size_t rb = ((size_t)b * H + gi) * H;
    float4 a, c;
    a.x=dUr[rr][0]; a.y=dUr[rr][1]; a.z=dUr[rr][2]; a.w=dUr[rr][3];
    c.x=dUr[rr][4]; c.y=dUr[rr][5]; c.z=dUr[rr][6]; c.w=dUr[rr][7];
    ((float4*)(out + DU_OFF + rb))[lane]      = a;
    ((float4*)(out + DU_OFF + rb))[32 + lane] = c;
    a.x=tEr[rr][0]; a.y=tEr[rr][1]; a.z=tEr[rr][2]; a.w=tEr[rr][3];
    c.x=tEr[rr][4]; c.y=tEr[rr][5]; c.z=tEr[rr][6]; c.w=tEr[rr][7];
    ((float4*)(out + TEE_OFF + rb))[lane]      = a;
    ((float4*)(out + TEE_OFF + rb))[32 + lane] = c;
  }
}

extern "C" void kernel_launch(void* const* d_in, const int* in_sizes, int n_in,
                              void* d_out, int out_size) {
  (void)in_sizes; (void)n_in; (void)out_size;
  const float* x_in   = (const float*)d_in[0];
  const float* h0     = (const float*)d_in[1];
  const float* v0     = (const float*)d_in[2];
  const float* dU0    = (const float*)d_in[3];
  const float* te0    = (const float*)d_in[4];
  const float* tE0    = (const float*)d_in[5];
  const float* Wx2h   = (const float*)d_in[6];
  const float* bx2h   = (const float*)d_in[7];
  const float* Wh2h   = (const float*)d_in[8];
  const float* bh2h   = (const float*)d_in[9];
  const float* lnxg   = (const float*)d_in[10];
  const float* lnxb   = (const float*)d_in[11];
  const float* lnhg   = (const float*)d_in[12];
  const float* lnhb   = (const float*)d_in[13];
  const float* Wh2mod = (const float*)d_in[14];
  const float* bh2mod = (const float*)d_in[15];
  const float* Wmod2h = (const float*)d_in[16];
  const float* bmod2h = (const float*)d_in[17];
  const float* alpha  = (const float*)d_in[18];
  const float* tauU   = (const float*)d_in[19];
  float* out = (float*)d_out;

  cudaFuncSetAttribute(sgru_persistent,
                       cudaFuncAttributeMaxDynamicSharedMemorySize,
                       (int)sizeof(SM));
  sgru_persistent<<<B * 8, 256, sizeof(SM)>>>(
      x_in, h0, v0, dU0, te0, tE0, Wx2h, bx2h, Wh2h, bh2h,
      lnxg, lnxb, lnhg, lnhb, Wh2mod, bh2mod, Wmod2h, bmod2h,
      alpha, tauU, out);
}

// round 3
// speedup vs baseline: 2.1775x; 1.2206x over previous
#include <cuda_runtime.h>
#include <math.h>
#include <stdint.h>

namespace {
constexpr int H  = 256;
constexpr int I  = 128;
constexpr int R  = 32;
constexpr int B  = 16;
constexpr int T  = 48;
constexpr int H3 = 768;

constexpr long V_OFF    = 0;
constexpr long H_OFF    = V_OFF  + (long)B * H;
constexpr long DU_OFF   = H_OFF  + (long)B * H;
constexpr long TE_OFF   = DU_OFF + (long)B * H * H;
constexpr long TEE_OFF  = TE_OFF + (long)B * H;
constexpr long OUTS_OFF = TEE_OFF + (long)B * H * H;
constexpr long MODS_OFF = OUTS_OFF + (long)T * B * H;
}

__device__ float g_Wx[(size_t)T * B * H3];   // LN(x @ Wx2h^T + b), prologue

struct SM {
  float Ws[96 * 256];    // W_h2h slice (prologue: W_x2h slice)
  float Wm[32 * 256];    // W_h2mod
  float whx[2][H3];      // DSMEM-exchanged Wh (+bias), double buffered
  float plx[2][H];       // DSMEM-exchanged plastic
  float bh[H3];
  float lng[H3];
  float lnb[H3];
  float h[H];
  float te[H];
  float mod[R];
  float2 red[16];
  float wm2[2 * R];
  float bhm[R];
};

__device__ __forceinline__ float sigm(float x) { return 1.0f / (1.0f + __expf(-x)); }

__device__ __forceinline__ void cluster_sync_() {
  asm volatile("barrier.cluster.arrive.aligned;\n\tbarrier.cluster.wait.aligned;" ::: "memory");
}

__device__ __forceinline__ uint32_t smem_u32(const void* p) {
  return (uint32_t)__cvta_generic_to_shared(p);
}

__device__ __forceinline__ uint32_t mapa_u32(uint32_t addr, uint32_t peer) {
  uint32_t r;
  asm("mapa.shared::cluster.u32 %0, %1, %2;" : "=r"(r) : "r"(addr), "r"(peer));
  return r;
}

__device__ __forceinline__ void st_cluster_f32x2(uint32_t addr, float a, float b) {
  asm volatile("st.shared::cluster.v2.f32 [%0], {%1, %2};"
               :: "r"(addr), "f"(a), "f"(b) : "memory");
}

__device__ __forceinline__ float dot4(float4 a, const float* h) {
  return a.x * h[0] + a.y * h[1] + a.z * h[2] + a.w * h[3];
}

__global__ void __cluster_dims__(8, 1, 1) __launch_bounds__(512, 1)
sgru_persistent(const float* __restrict__ x_in,
                const float* __restrict__ h0,
                const float* __restrict__ v0,
                const float* __restrict__ dU0,
                const float* __restrict__ te0,
                const float* __restrict__ tE0,
                const float* __restrict__ Wx2h,
                const float* __restrict__ bx2h,
                const float* __restrict__ Wh2h,
                const float* __restrict__ bh2h,
                const float* __restrict__ lnxg,
                const float* __restrict__ lnxb,
                const float* __restrict__ lnhg,
                const float* __restrict__ lnhb,
                const float* __restrict__ Wh2mod,
                const float* __restrict__ bh2mod,
                const float* __restrict__ Wmod2h,
                const float* __restrict__ bmod2h,
                const float* __restrict__ alpha,
                const float* __restrict__ tauU,
                float* __restrict__ out)
{
  extern __shared__ unsigned char smem_raw[];
  SM* S = reinterpret_cast<SM*>(smem_raw);
  const int tid  = threadIdx.x;
  const int wid  = tid >> 5;
  const int lane = tid & 31;
  const int rank = blockIdx.x & 7;
  const int b    = blockIdx.x >> 3;

  const float a0      = alpha[0];
  const float sp_a    = (a0 > 0.f) ? (a0 + log1pf(expf(-a0))) : log1pf(expf(a0));
  const float inv_spa = 1.0f / sp_a;
  const float tau     = sigm(tauU[0]);
  const float bm0     = bmod2h[0];
  const float bm1     = bmod2h[1];

  // ================= prologue: Wx = x @ Wx2h^T + b (raw) =====================
  {
    const float4* WxA = (const float4*)(Wx2h + (size_t)96 * rank * I);
    float4* Ws4w = (float4*)S->Ws;
    for (int i = tid; i < 96 * I / 4; i += 512) Ws4w[i] = WxA[i];
  }
  __syncthreads();
  {
    const float4* Ws4c = (const float4*)S->Ws;
    for (int it = 0; it < 3; ++it) {
      int t = wid + 16 * it;
      float4 x4 = ((const float4*)x_in)[(size_t)(t * B + b) * 32 + lane];
      for (int g = 0; g < 6; ++g) {
        float acc[16];
#pragma unroll
        for (int k = 0; k < 16; ++k) {
          float4 w = Ws4c[(g * 16 + k) * 32 + lane];
          acc[k] = w.x * x4.x + w.y * x4.y + w.z * x4.z + w.w * x4.w;
        }
        // fold 16 -> 2 (values: v = k + 2*b4 + 4*b8 + 8*b16)
#pragma unroll
        for (int k = 0; k < 8; ++k) {
          float a = (lane & 16) ? acc[k + 8] : acc[k];
          float c = (lane & 16) ? acc[k] : acc[k + 8];
          acc[k] = a + __shfl_xor_sync(~0u, c, 16);
        }
#pragma unroll
        for (int k = 0; k < 4; ++k) {
          float a = (lane & 8) ? acc[k + 4] : acc[k];
          float c = (lane & 8) ? acc[k] : acc[k + 4];
          acc[k] = a + __shfl_xor_sync(~0u, c, 8);
        }
#pragma unroll
        for (int k = 0; k < 2; ++k) {
          float a = (lane & 4) ? acc[k + 2] : acc[k];
          float c = (lane & 4) ? acc[k] : acc[k + 2];
          acc[k] = a + __shfl_xor_sync(~0u, c, 4);
        }
#pragma unroll
        for (int o = 2; o; o >>= 1) {
          acc[0] += __shfl_xor_sync(~0u, acc[0], o);
          acc[1] += __shfl_xor_sync(~0u, acc[1], o);
        }
        if ((lane & 3) == 0) {
          int p = (lane >> 2) & 7;                 // pair {2p, 2p+1}
          int o = 96 * rank + g * 16 + 2 * p;
          float2 bias = *(const float2*)&bx2h[o];
          float2 val = make_float2(acc[0] + bias.x, acc[1] + bias.y);
          *(float2*)&g_Wx[(size_t)(t * B + b) * H3 + o] = val;
        }
      }
    }
  }
  cluster_sync_();

  // ================= prologue LN over g_Wx ===================================
  for (int t = rank; t < T; t += 8) {
    float* base = &g_Wx[(size_t)(t * B + b) * H3];
    float e0 = base[tid];
    float e1 = (tid < 256) ? base[512 + tid] : 0.f;
    float s1 = e0 + e1, s2 = e0 * e0 + e1 * e1;
#pragma unroll
    for (int o = 16; o; o >>= 1) {
      s1 += __shfl_xor_sync(~0u, s1, o);
      s2 += __shfl_xor_sync(~0u, s2, o);
    }
    if (lane == 0) S->red[wid] = make_float2(s1, s2);
    __syncthreads();
    float ssum = 0.f, ssq = 0.f;
#pragma unroll
    for (int i = 0; i < 16; ++i) { float2 rr = S->red[i]; ssum += rr.x; ssq += rr.y; }
    float mu   = ssum * (1.0f / H3);
    float var  = ssq * (1.0f / H3) - mu * mu;
    float rstd = rsqrtf(var + 1e-5f);
    base[tid] = (e0 - mu) * rstd * lnxg[tid] + lnxb[tid];
    if (tid < 256)
      base[512 + tid] = (e1 - mu) * rstd * lnxg[512 + tid] + lnxb[512 + tid];
    __syncthreads();
  }

  // ================= load main-loop smem + register state ===================
  {
    const float4* WhA = (const float4*)(Wh2h + (size_t)64 * rank * H);
    const float4* WhB = (const float4*)(Wh2h + (size_t)(512 + 32 * rank) * H);
    const float4* Wm4 = (const float4*)Wh2mod;
    float4* Ws4w = (float4*)S->Ws;
    float4* Wm4w = (float4*)S->Wm;
    for (int i = tid; i < 64 * 64; i += 512) Ws4w[i] = WhA[i];
    for (int i = tid; i < 32 * 64; i += 512) Ws4w[64 * 64 + i] = WhB[i];
    for (int i = tid; i < 32 * 64; i += 512) Wm4w[i] = Wm4[i];
    for (int i = tid; i < H3; i += 512) {
      S->bh[i] = bh2h[i]; S->lng[i] = lnhg[i]; S->lnb[i] = lnhb[i];
    }
    if (tid < 2 * R) S->wm2[tid] = Wmod2h[tid];
    if (tid < R)     S->bhm[tid] = bh2mod[tid];
  }
  float h_own = 0.f, v_own = 0.f, te_own = 0.f;
  if (tid < 256) {
    h_own  = h0[b * H + tid];
    v_own  = v0[b * H + tid];
    te_own = te0[b * H + tid];
    S->h[tid]  = h_own;
    S->te[tid] = te_own;
  }

  // thread owns rows gi = 32*rank + wid*2 + rr, cols {4*lane..+3, 128+4*lane..+3}
  float dUr[2][8], tEr[2][8], upr[2][8], lor[2][8];
#pragma unroll
  for (int rr = 0; rr < 2; ++rr) {
    int gi = 32 * rank + wid * 2 + rr;
    const float4* du4 = (const float4*)(dU0 + ((size_t)b * H + gi) * H);
    const float4* tE4 = (const float4*)(tE0 + ((size_t)b * H + gi) * H);
    const float4* wv4 = (const float4*)(Wh2h + (size_t)(512 + gi) * H);
    float4 a, c;
    a = du4[lane]; c = du4[32 + lane];
    dUr[rr][0]=a.x; dUr[rr][1]=a.y; dUr[rr][2]=a.z; dUr[rr][3]=a.w;
    dUr[rr][4]=c.x; dUr[rr][5]=c.y; dUr[rr][6]=c.z; dUr[rr][7]=c.w;
    a = tE4[lane]; c = tE4[32 + lane];
    tEr[rr][0]=a.x; tEr[rr][1]=a.y; tEr[rr][2]=a.z; tEr[rr][3]=a.w;
    tEr[rr][4]=c.x; tEr[rr][5]=c.y; tEr[rr][6]=c.z; tEr[rr][7]=c.w;
    a = wv4[lane]; c = wv4[32 + lane];
    float wv[8] = {a.x,a.y,a.z,a.w,c.x,c.y,c.z,c.w};
#pragma unroll
    for (int j = 0; j < 8; ++j) {
      upr[rr][j] =  fmaxf(1.f - wv[j], 0.f) * inv_spa;
      lor[rr][j] = -fmaxf(1.f + wv[j], 0.f) * inv_spa;
    }
  }

  const uint32_t whx_peer = mapa_u32(smem_u32(&S->whx[0][0]), lane & 7);
  const uint32_t plx_peer = mapa_u32(smem_u32(&S->plx[0][0]), lane & 7);

  cluster_sync_();

  float hreg[8], tereg[8];
  {
    const float4* h4 = (const float4*)S->h;
    const float4* t4 = (const float4*)S->te;
    float4 a = h4[lane], c = h4[32 + lane];
    hreg[0]=a.x; hreg[1]=a.y; hreg[2]=a.z; hreg[3]=a.w;
    hreg[4]=c.x; hreg[5]=c.y; hreg[6]=c.z; hreg[7]=c.w;
    a = t4[lane]; c = t4[32 + lane];
    tereg[0]=a.x; tereg[1]=a.y; tereg[2]=a.z; tereg[3]=a.w;
    tereg[4]=c.x; tereg[5]=c.y; tereg[6]=c.z; tereg[7]=c.w;
  }

  const float4* Ws4 = (const float4*)S->Ws;
  const float4* Wm4 = (const float4*)S->Wm;

  // ================= main scan ==============================================
  int par = 0;
  for (int t = 0; t < T; ++t, par ^= 1) {
    // prefetch x-projection (consumed after the cluster sync)
    float wx0 = 0.f, wx1 = 0.f, wx2 = 0.f;
    if (tid < 256) {
      const float* wxp = &g_Wx[(size_t)(t * B + b) * H3];
      wx0 = __ldcg(wxp + tid);
      wx1 = __ldcg(wxp + tid + 256);
      wx2 = __ldcg(wxp + tid + 512);
    }

    // ---- phase 1: 6 Wh rows + 2 plastic rows per warp ----
    float acc[8];
#pragma unroll
    for (int rq = 0; rq < 6; ++rq) {
      int q = wid * 6 + rq;
      acc[rq] = dot4(Ws4[q * 64 + lane], hreg) + dot4(Ws4[q * 64 + 32 + lane], hreg + 4);
    }
#pragma unroll
    for (int rr = 0; rr < 2; ++rr) {
      float p = 0.f;
#pragma unroll
      for (int j = 0; j < 8; ++j) p += dUr[rr][j] * hreg[j];
      acc[6 + rr] = p * sp_a;
    }
    // fold 8 -> 2 (v = k + 2*b8 + 4*b16), finish over lanes 4,2,1
#pragma unroll
    for (int k = 0; k < 4; ++k) {
      float a = (lane & 16) ? acc[k + 4] : acc[k];
      float c = (lane & 16) ? acc[k] : acc[k + 4];
      acc[k] = a + __shfl_xor_sync(~0u, c, 16);
    }
#pragma unroll
    for (int k = 0; k < 2; ++k) {
      float a = (lane & 8) ? acc[k + 2] : acc[k];
      float c = (lane & 8) ? acc[k] : acc[k + 2];
      acc[k] = a + __shfl_xor_sync(~0u, c, 8);
    }
#pragma unroll
    for (int o = 4; o; o >>= 1) {
      acc[0] += __shfl_xor_sync(~0u, acc[0], o);
      acc[1] += __shfl_xor_sync(~0u, acc[1], o);
    }
    {
      int p = (lane >> 3) & 3;        // pair of values {2p, 2p+1}
      if (p < 3) {
        int q0 = wid * 6 + 2 * p;
        int o0 = (q0 < 64) ? (64 * rank + q0) : (512 + 32 * rank + (q0 - 64));
        float2 bias = *(const float2*)&S->bh[o0];
        st_cluster_f32x2(whx_peer + (uint32_t)(par * H3 + o0) * 4u,
                         acc[0] + bias.x, acc[1] + bias.y);
      } else {
        int g0 = 32 * rank + wid * 2;
        st_cluster_f32x2(plx_peer + (uint32_t)(par * H + g0) * 4u, acc[0], acc[1]);
      }
    }
    cluster_sync_();

    // ---- phase 2: LN partials by all 16 warps ----
    float w0 = S->whx[par][tid];
    float w2 = (tid < 256) ? (S->whx[par][512 + tid] + S->plx[par][tid]) : 0.f;
    float s1 = w0 + w2, s2 = w0 * w0 + w2 * w2;
#pragma unroll
    for (int o = 16; o; o >>= 1) {
      s1 += __shfl_xor_sync(~0u, s1, o);
      s2 += __shfl_xor_sync(~0u, s2, o);
    }
    if (lane == 0) S->red[wid] = make_float2(s1, s2);
    __syncthreads();                                    // (A)
    float ssum = 0.f, ssq = 0.f;
#pragma unroll
    for (int i = 0; i < 16; ++i) { float2 rr2 = S->red[i]; ssum += rr2.x; ssq += rr2.y; }
    float mu   = ssum * (1.0f / H3);
    float var  = ssq * (1.0f / H3) - mu * mu;
    float rstd = rsqrtf(var + 1e-5f);

    if (tid < 256) {
      float w1 = S->whx[par][256 + tid];
      float pre0 = (w0 - mu) * rstd * S->lng[tid]       + S->lnb[tid]       + wx0;
      float pre1 = (w1 - mu) * rstd * S->lng[tid + 256] + S->lnb[tid + 256] + wx1;
      float pre2 = (w2 - mu) * rstd * S->lng[tid + 512] + S->lnb[tid + 512] + wx2;
      float z  = sigm(pre0);
      float r  = sigm(pre1);
      float vn = v_own + z * (pre2 - v_own);
      float hn = fmaxf(vn, 0.f);
      float tn = te_own + r * (h_own - te_own);         // OLD h
      v_own = vn; h_own = hn; te_own = tn;
      S->h[tid]  = hn;
      S->te[tid] = tn;
      if (rank == 0) out[OUTS_OFF + (size_t)(t * B + b) * H + tid] = hn;
    }
    __syncthreads();                                    // (B)

    // reload column registers (new h / te)
    {
      const float4* h4 = (const float4*)S->h;
      const float4* t4 = (const float4*)S->te;
      float4 a = h4[lane], c = h4[32 + lane];
      hreg[0]=a.x; hreg[1]=a.y; hreg[2]=a.z; hreg[3]=a.w;
      hreg[4]=c.x; hreg[5]=c.y; hreg[6]=c.z; hreg[7]=c.w;
      a = t4[lane]; c = t4[32 + lane];
      tereg[0]=a.x; tereg[1]=a.y; tereg[2]=a.z; tereg[3]=a.w;
      tereg[4]=c.x; tereg[5]=c.y; tereg[6]=c.z; tereg[7]=c.w;
    }

    // ---- mod = relu(h_new @ Wm^T + b): 2 rows per warp ----
    {
      float m0 = dot4(Wm4[(wid * 2) * 64 + lane], hreg)
               + dot4(Wm4[(wid * 2) * 64 + 32 + lane], hreg + 4);
      float m1 = dot4(Wm4[(wid * 2 + 1) * 64 + lane], hreg)
               + dot4(Wm4[(wid * 2 + 1) * 64 + 32 + lane], hreg + 4);
      float a = (lane & 16) ? m1 : m0;
      float c = (lane & 16) ? m0 : m1;
      float vsum = a + __shfl_xor_sync(~0u, c, 16);
#pragma unroll
      for (int o = 8; o; o >>= 1) vsum += __shfl_xor_sync(~0u, vsum, o);
      if ((lane & 15) == 0) {
        int j = wid * 2 + ((lane >> 4) & 1);
        S->mod[j] = fmaxf(vsum + S->bhm[j], 0.f);
      }
    }
    __syncthreads();                                    // (C)

    // s, m computed redundantly per warp
    float mj = S->mod[lane];
    float t0 = mj * S->wm2[lane];
    float t1 = mj * S->wm2[32 + lane];
#pragma unroll
    for (int o = 16; o; o >>= 1) {
      t0 += __shfl_xor_sync(~0u, t0, o);
      t1 += __shfl_xor_sync(~0u, t1, o);
    }
    float s = sigm(t0 + bm0);
    float m = t1 + bm1;
    if (rank == 0 && tid < R)
      out[MODS_OFF + (size_t)(t * B + b) * R + tid] = S->mod[tid];

    // ---- phase 3: dU / tE update + clip (2 rows/thread-warp) ----
#pragma unroll
    for (int rr = 0; rr < 2; ++rr) {
      int gi = 32 * rank + wid * 2 + rr;
      float hni  = S->h[gi];
      float teni = S->te[gi];
#pragma unroll
      for (int j = 0; j < 8; ++j) {
        float outer = hni * tereg[j] - teni * hreg[j];
        float E = tEr[rr][j] + s * (outer - tEr[rr][j]);
        tEr[rr][j] = E;
        float d = dUr[rr][j] + tau * (m * E - dUr[rr][j]);
        dUr[rr][j] = fminf(fmaxf(d, lor[rr][j]), upr[rr][j]);
      }
    }
  }

  // ================= epilogue ===============================================
  if (rank == 0 && tid < 256) {
    out[V_OFF  + b * H + tid] = v_own;
    out[H_OFF  + b * H + tid] = h_own;
    out[TE_OFF + b * H + tid] = te_own;
  }
#pragma unroll
  for (int rr = 0; rr < 2; ++rr) {
    int gi = 32 * rank + wid * 2 + rr;
    size_t rb = ((size_t)b * H + gi) * H;
    float4 a, c;
    a.x=dUr[rr][0]; a.y=dUr[rr][1]; a.z=dUr[rr][2]; a.w=dUr[rr][3];
    c.x=dUr[rr][4]; c.y=dUr[rr][5]; c.z=dUr[rr][6]; c.w=dUr[rr][7];
    ((float4*)(out + DU_OFF + rb))[lane]      = a;
    ((float4*)(out + DU_OFF + rb))[32 + lane] = c;
    a.x=tEr[rr][0]; a.y=tEr[rr][1]; a.z=tEr[rr][2]; a.w=tEr[rr][3];
    c.x=tEr[rr][4]; c.y=tEr[rr][5]; c.z=tEr[rr][6]; c.w=tEr[rr][7];
    ((float4*)(out + TEE_OFF + rb))[lane]      = a;
    ((float4*)(out + TEE_OFF + rb))[32 + lane] = c;
  }
}

extern "C" void kernel_launch(void* const* d_in, const int* in_sizes, int n_in,
                              void* d_out, int out_size) {
  (void)in_sizes; (void)n_in; (void)out_size;
  const float* x_in   = (const float*)d_in[0];
  const float* h0     = (const float*)d_in[1];
  const float* v0     = (const float*)d_in[2];
  const float* dU0    = (const float*)d_in[3];
  const float* te0    = (const float*)d_in[4];
  const float* tE0    = (const float*)d_in[5];
  const float* Wx2h   = (const float*)d_in[6];
  const float* bx2h   = (const float*)d_in[7];
  const float* Wh2h   = (const float*)d_in[8];
  const float* bh2h   = (const float*)d_in[9];
  const float* lnxg   = (const float*)d_in[10];
  const float* lnxb   = (const float*)d_in[11];
  const float* lnhg   = (const float*)d_in[12];
  const float* lnhb   = (const float*)d_in[13];
  const float* Wh2mod = (const float*)d_in[14];
  const float* bh2mod = (const float*)d_in[15];
  const float* Wmod2h = (const float*)d_in[16];
  const float* bmod2h = (const float*)d_in[17];
  const float* alpha  = (const float*)d_in[18];
  const float* tauU   = (const float*)d_in[19];
  float* out = (float*)d_out;

  cudaFuncSetAttribute(sgru_persistent,
                       cudaFuncAttributeMaxDynamicSharedMemorySize,
                       (int)sizeof(SM));
  sgru_persistent<<<B * 8, 512, sizeof(SM)>>>(
      x_in, h0, v0, dU0, te0, tE0, Wx2h, bx2h, Wh2h, bh2h,
      lnxg, lnxb, lnhg, lnhb, Wh2mod, bh2mod, Wmod2h, bmod2h,
      alpha, tauU, out);
}

// round 4
// speedup vs baseline: 2.2375x; 1.0275x over previous
#include <cuda_runtime.h>
#include <math.h>
#include <stdint.h>

namespace {
constexpr int H  = 256;
constexpr int I  = 128;
constexpr int R  = 32;
constexpr int B  = 16;
constexpr int T  = 48;
constexpr int H3 = 768;

constexpr long V_OFF    = 0;
constexpr long H_OFF    = V_OFF  + (long)B * H;
constexpr long DU_OFF   = H_OFF  + (long)B * H;
constexpr long TE_OFF   = DU_OFF + (long)B * H * H;
constexpr long TEE_OFF  = TE_OFF + (long)B * H;
constexpr long OUTS_OFF = TEE_OFF + (long)B * H * H;
constexpr long MODS_OFF = OUTS_OFF + (long)T * B * H;
}

__device__ float g_Wx[(size_t)T * B * H3];   // LN(x @ Wx2h^T + b), prologue

struct SM {
  float Ws[96 * 256];      // W_h2h slice, reordered: [0:32)=z, [32:64)=r, [64:96)=dv rows
  float Wm[32 * 256];      // W_h2mod
  float  whx[2][H3];       // DSMEM-exchanged pre-LN vector (bias+plastic included)
  float2 stats[2][128];    // DSMEM-exchanged per-warp (sum, sumsq) partials
  float h[H];
  float te[H];
  float mod[R];
  float2 modred[16];       // per-warp (t0,t1) partials for s/m
  float2 red[16];          // prologue LN
};

__device__ __forceinline__ float sigm(float x) { return 1.0f / (1.0f + __expf(-x)); }

__device__ __forceinline__ void cluster_sync_() {
  asm volatile("barrier.cluster.arrive.aligned;\n\tbarrier.cluster.wait.aligned;" ::: "memory");
}

__device__ __forceinline__ uint32_t smem_u32(const void* p) {
  return (uint32_t)__cvta_generic_to_shared(p);
}

__device__ __forceinline__ uint32_t mapa_u32(uint32_t addr, uint32_t peer) {
  uint32_t r;
  asm("mapa.shared::cluster.u32 %0, %1, %2;" : "=r"(r) : "r"(addr), "r"(peer));
  return r;
}

__device__ __forceinline__ void st_cluster_f32x2(uint32_t addr, float a, float b) {
  asm volatile("st.shared::cluster.v2.f32 [%0], {%1, %2};"
               :: "r"(addr), "f"(a), "f"(b) : "memory");
}

__device__ __forceinline__ float dot4(float4 a, const float* h) {
  return a.x * h[0] + a.y * h[1] + a.z * h[2] + a.w * h[3];
}

__global__ void __cluster_dims__(8, 1, 1) __launch_bounds__(512, 1)
sgru_persistent(const float* __restrict__ x_in,
                const float* __restrict__ h0,
                const float* __restrict__ v0,
                const float* __restrict__ dU0,
                const float* __restrict__ te0,
                const float* __restrict__ tE0,
                const float* __restrict__ Wx2h,
                const float* __restrict__ bx2h,
                const float* __restrict__ Wh2h,
                const float* __restrict__ bh2h,
                const float* __restrict__ lnxg,
                const float* __restrict__ lnxb,
                const float* __restrict__ lnhg,
                const float* __restrict__ lnhb,
                const float* __restrict__ Wh2mod,
                const float* __restrict__ bh2mod,
                const float* __restrict__ Wmod2h,
                const float* __restrict__ bmod2h,
                const float* __restrict__ alpha,
                const float* __restrict__ tauU,
                float* __restrict__ out)
{
  extern __shared__ unsigned char smem_raw[];
  SM* S = reinterpret_cast<SM*>(smem_raw);
  const int tid  = threadIdx.x;
  const int wid  = tid >> 5;
  const int lane = tid & 31;
  const int rank = blockIdx.x & 7;
  const int b    = blockIdx.x >> 3;
  const int gi0  = 32 * rank + 2 * wid;   // this warp's slot base (2 slots)

  const float a0      = alpha[0];
  const float sp_a    = (a0 > 0.f) ? (a0 + log1pf(expf(-a0))) : log1pf(expf(a0));
  const float inv_spa = 1.0f / sp_a;
  const float tau     = sigm(tauU[0]);
  const float bm0     = bmod2h[0];
  const float bm1     = bmod2h[1];

  // ================= prologue: Wx = x @ Wx2h^T + b (raw) =====================
  {
    const float4* WxA = (const float4*)(Wx2h + (size_t)96 * rank * I);
    float4* Ws4w = (float4*)S->Ws;
    for (int i = tid; i < 96 * I / 4; i += 512) Ws4w[i] = WxA[i];
  }
  __syncthreads();
  {
    const float4* Ws4c = (const float4*)S->Ws;
    for (int it = 0; it < 3; ++it) {
      int t = wid + 16 * it;
      float4 x4 = ((const float4*)x_in)[(size_t)(t * B + b) * 32 + lane];
      for (int g = 0; g < 6; ++g) {
        float acc[16];
#pragma unroll
        for (int k = 0; k < 16; ++k) {
          float4 w = Ws4c[(g * 16 + k) * 32 + lane];
          acc[k] = w.x * x4.x + w.y * x4.y + w.z * x4.z + w.w * x4.w;
        }
#pragma unroll
        for (int k = 0; k < 8; ++k) {
          float a = (lane & 16) ? acc[k + 8] : acc[k];
          float c = (lane & 16) ? acc[k] : acc[k + 8];
          acc[k] = a + __shfl_xor_sync(~0u, c, 16);
        }
#pragma unroll
        for (int k = 0; k < 4; ++k) {
          float a = (lane & 8) ? acc[k + 4] : acc[k];
          float c = (lane & 8) ? acc[k] : acc[k + 4];
          acc[k] = a + __shfl_xor_sync(~0u, c, 8);
        }
#pragma unroll
        for (int k = 0; k < 2; ++k) {
          float a = (lane & 4) ? acc[k + 2] : acc[k];
          float c = (lane & 4) ? acc[k] : acc[k + 2];
          acc[k] = a + __shfl_xor_sync(~0u, c, 4);
        }
#pragma unroll
        for (int o = 2; o; o >>= 1) {
          acc[0] += __shfl_xor_sync(~0u, acc[0], o);
          acc[1] += __shfl_xor_sync(~0u, acc[1], o);
        }
        if ((lane & 3) == 0) {
          int p = (lane >> 2) & 7;
          int o = 96 * rank + g * 16 + 2 * p;
          float2 bias = *(const float2*)&bx2h[o];
          float2 val = make_float2(acc[0] + bias.x, acc[1] + bias.y);
          *(float2*)&g_Wx[(size_t)(t * B + b) * H3 + o] = val;
        }
      }
    }
  }
  cluster_sync_();

  // ================= prologue LN over g_Wx ===================================
  for (int t = rank; t < T; t += 8) {
    float* base = &g_Wx[(size_t)(t * B + b) * H3];
    float e0 = base[tid];
    float e1 = (tid < 256) ? base[512 + tid] : 0.f;
    float s1 = e0 + e1, s2 = e0 * e0 + e1 * e1;
#pragma unroll
    for (int o = 16; o; o >>= 1) {
      s1 += __shfl_xor_sync(~0u, s1, o);
      s2 += __shfl_xor_sync(~0u, s2, o);
    }
    if (lane == 0) S->red[wid] = make_float2(s1, s2);
    __syncthreads();
    float ssum = 0.f, ssq = 0.f;
#pragma unroll
    for (int i = 0; i < 16; ++i) { float2 rr = S->red[i]; ssum += rr.x; ssq += rr.y; }
    float mu   = ssum * (1.0f / H3);
    float var  = ssq * (1.0f / H3) - mu * mu;
    float rstd = rsqrtf(var + 1e-5f);
    base[tid] = (e0 - mu) * rstd * lnxg[tid] + lnxb[tid];
    if (tid < 256)
      base[512 + tid] = (e1 - mu) * rstd * lnxg[512 + tid] + lnxb[512 + tid];
    __syncthreads();
  }

  // ================= load main-loop smem + register state ===================
  {
    // Ws reordered: local row q -> global row (q>>5)*256 + 32*rank + (q&31)
    float4* Ws4w = (float4*)S->Ws;
    for (int i = tid; i < 96 * 64; i += 512) {
      int q = i >> 6, c4 = i & 63;
      int grow = ((q >> 5) << 8) + 32 * rank + (q & 31);
      Ws4w[i] = ((const float4*)(Wh2h + (size_t)grow * H))[c4];
    }
    const float4* Wm4s = (const float4*)Wh2mod;
    float4* Wm4w = (float4*)S->Wm;
    for (int i = tid; i < 32 * 64; i += 512) Wm4w[i] = Wm4s[i];
  }
  float h_own = 0.f, v_own = 0.f, te_own = 0.f;
  float g0 = 0.f, g1 = 0.f, g2 = 0.f, lb0 = 0.f, lb1 = 0.f, lb2 = 0.f;
  if (tid < 256) {
    h_own  = h0[b * H + tid];
    v_own  = v0[b * H + tid];
    te_own = te0[b * H + tid];
    S->h[tid]  = h_own;
    S->te[tid] = te_own;
    g0 = lnhg[tid]; g1 = lnhg[tid + 256]; g2 = lnhg[tid + 512];
    lb0 = lnhb[tid]; lb1 = lnhb[tid + 256]; lb2 = lnhb[tid + 512];
  }

  // per-lane fold pair p and preloaded bias pair
  const int pgrp = (lane >> 3) & 3;
  float pb0 = 0.f, pb1 = 0.f;
  if (pgrp < 3) {
    pb0 = bh2h[256 * pgrp + gi0];
    pb1 = bh2h[256 * pgrp + gi0 + 1];
  }
  // preloaded s/m weights (warp-uniform) and mod bias (per half-warp)
  const float wsA = Wmod2h[2 * wid], wsB = Wmod2h[2 * wid + 1];
  const float wmA = Wmod2h[R + 2 * wid], wmB = Wmod2h[R + 2 * wid + 1];
  const int   mrow = 2 * wid + ((lane >> 4) & 1);
  const float bhm_l = bh2mod[mrow];

  // dU / tE rows gi0, gi0+1 ; cols {4*lane..+3, 128+4*lane..+3}
  float dUr[2][8], tEr[2][8], upr[2][8], lor[2][8];
#pragma unroll
  for (int rr = 0; rr < 2; ++rr) {
    int gi = gi0 + rr;
    const float4* du4 = (const float4*)(dU0 + ((size_t)b * H + gi) * H);
    const float4* tE4 = (const float4*)(tE0 + ((size_t)b * H + gi) * H);
    const float4* wv4 = (const float4*)(Wh2h + (size_t)(512 + gi) * H);
    float4 a, c;
    a = du4[lane]; c = du4[32 + lane];
    dUr[rr][0]=a.x; dUr[rr][1]=a.y; dUr[rr][2]=a.z; dUr[rr][3]=a.w;
    dUr[rr][4]=c.x; dUr[rr][5]=c.y; dUr[rr][6]=c.z; dUr[rr][7]=c.w;
    a = tE4[lane]; c = tE4[32 + lane];
    tEr[rr][0]=a.x; tEr[rr][1]=a.y; tEr[rr][2]=a.z; tEr[rr][3]=a.w;
    tEr[rr][4]=c.x; tEr[rr][5]=c.y; tEr[rr][6]=c.z; tEr[rr][7]=c.w;
    a = wv4[lane]; c = wv4[32 + lane];
    float wv[8] = {a.x,a.y,a.z,a.w,c.x,c.y,c.z,c.w};
#pragma unroll
    for (int j = 0; j < 8; ++j) {
      upr[rr][j] =  fmaxf(1.f - wv[j], 0.f) * inv_spa;
      lor[rr][j] = -fmaxf(1.f + wv[j], 0.f) * inv_spa;
    }
  }

  const uint32_t whx_peer   = mapa_u32(smem_u32(&S->whx[0][0]),   lane & 7);
  const uint32_t stats_peer = mapa_u32(smem_u32(&S->stats[0][0]), lane & 7);

  cluster_sync_();

  float hreg[8], tereg[8];
  {
    const float4* h4 = (const float4*)S->h;
    const float4* t4 = (const float4*)S->te;
    float4 a = h4[lane], c = h4[32 + lane];
    hreg[0]=a.x; hreg[1]=a.y; hreg[2]=a.z; hreg[3]=a.w;
    hreg[4]=c.x; hreg[5]=c.y; hreg[6]=c.z; hreg[7]=c.w;
    a = t4[lane]; c = t4[32 + lane];
    tereg[0]=a.x; tereg[1]=a.y; tereg[2]=a.z; tereg[3]=a.w;
    tereg[4]=c.x; tereg[5]=c.y; tereg[6]=c.z; tereg[7]=c.w;
  }

  // initial plastic partials: dU0 . h0 (per-lane partial over owned cols)
  float pp0 = 0.f, pp1 = 0.f;
#pragma unroll
  for (int j = 0; j < 8; ++j) { pp0 += dUr[0][j] * hreg[j]; pp1 += dUr[1][j] * hreg[j]; }

  const float4* Ws4 = (const float4*)S->Ws;
  const float4* Wm4 = (const float4*)S->Wm;

  // ================= main scan ==============================================
  int par = 0;
  for (int t = 0; t < T; ++t, par ^= 1) {
    // ---- A: GEMV 6 rows (z0,z1,r0,r1,dv0,dv1) + fused plastic ----
    float acc[8];
    acc[0] = dot4(Ws4[(2*wid)    * 64 + lane], hreg) + dot4(Ws4[(2*wid)    * 64 + 32 + lane], hreg + 4);
    acc[1] = dot4(Ws4[(2*wid+1)  * 64 + lane], hreg) + dot4(Ws4[(2*wid+1)  * 64 + 32 + lane], hreg + 4);
    acc[2] = dot4(Ws4[(32+2*wid) * 64 + lane], hreg) + dot4(Ws4[(32+2*wid) * 64 + 32 + lane], hreg + 4);
    acc[3] = dot4(Ws4[(33+2*wid) * 64 + lane], hreg) + dot4(Ws4[(33+2*wid) * 64 + 32 + lane], hreg + 4);
    acc[4] = dot4(Ws4[(64+2*wid) * 64 + lane], hreg) + dot4(Ws4[(64+2*wid) * 64 + 32 + lane], hreg + 4)
             + sp_a * pp0;
    acc[5] = dot4(Ws4[(65+2*wid) * 64 + lane], hreg) + dot4(Ws4[(65+2*wid) * 64 + 32 + lane], hreg + 4)
             + sp_a * pp1;
    acc[6] = 0.f; acc[7] = 0.f;

    // prefetch x-projection for phase 2
    float wx0 = 0.f, wx1 = 0.f, wx2 = 0.f;
    if (tid < 256) {
      const float* wxp = &g_Wx[(size_t)(t * B + b) * H3];
      wx0 = __ldcg(wxp + tid);
      wx1 = __ldcg(wxp + tid + 256);
      wx2 = __ldcg(wxp + tid + 512);
    }

    // ---- fold 8 -> 2 ----
#pragma unroll
    for (int k = 0; k < 4; ++k) {
      float a = (lane & 16) ? acc[k + 4] : acc[k];
      float c = (lane & 16) ? acc[k] : acc[k + 4];
      acc[k] = a + __shfl_xor_sync(~0u, c, 16);
    }
#pragma unroll
    for (int k = 0; k < 2; ++k) {
      float a = (lane & 8) ? acc[k + 2] : acc[k];
      float c = (lane & 8) ? acc[k] : acc[k + 2];
      acc[k] = a + __shfl_xor_sync(~0u, c, 8);
    }
#pragma unroll
    for (int o = 4; o; o >>= 1) {
      acc[0] += __shfl_xor_sync(~0u, acc[0], o);
      acc[1] += __shfl_xor_sync(~0u, acc[1], o);
    }
    // bias + warp stats (sum, sumsq over this warp's 6 values)
    acc[0] += pb0; acc[1] += pb1;                 // pb=0 for pgrp==3 (zero slots)
    float u = acc[0] + acc[1];
    float q = acc[0] * acc[0] + acc[1] * acc[1];
    u += __shfl_xor_sync(~0u, u, 8);  q += __shfl_xor_sync(~0u, q, 8);
    u += __shfl_xor_sync(~0u, u, 16); q += __shfl_xor_sync(~0u, q, 16);

    // ---- DSMEM stores: 3 value pairs + 1 stats pair, to peer (lane&7) ----
    if (pgrp < 3) {
      st_cluster_f32x2(whx_peer + (uint32_t)(par * H3 + 256 * pgrp + gi0) * 4u,
                       acc[0], acc[1]);
    } else {
      st_cluster_f32x2(stats_peer + (uint32_t)(par * 128 + rank * 16 + wid) * 8u, u, q);
    }
    cluster_sync_();

    // ---- D: stats combine (no barrier) + phase 2 ----
    if (tid < 256) {
      const float4* st4 = (const float4*)&S->stats[par][0];
      float4 A = st4[lane], Bv = st4[32 + lane];
      float su = A.x + A.z + Bv.x + Bv.z;
      float sq = A.y + A.w + Bv.y + Bv.w;
#pragma unroll
      for (int o = 16; o; o >>= 1) {
        su += __shfl_xor_sync(~0u, su, o);
        sq += __shfl_xor_sync(~0u, sq, o);
      }
      float mu   = su * (1.0f / H3);
      float var  = sq * (1.0f / H3) - mu * mu;
      float rstd = rsqrtf(var + 1e-5f);

      float w0 = S->whx[par][tid];
      float w1 = S->whx[par][256 + tid];
      float w2 = S->whx[par][512 + tid];
      float pre0 = (w0 - mu) * rstd * g0 + lb0 + wx0;
      float pre1 = (w1 - mu) * rstd * g1 + lb1 + wx1;
      float pre2 = (w2 - mu) * rstd * g2 + lb2 + wx2;
      float z  = sigm(pre0);
      float r  = sigm(pre1);
      float vn = v_own + z * (pre2 - v_own);
      float hn = fmaxf(vn, 0.f);
      float tn = te_own + r * (h_own - te_own);   // OLD h
      v_own = vn; h_own = hn; te_own = tn;
      S->h[tid]  = hn;
      S->te[tid] = tn;
      if (rank == 0) out[OUTS_OFF + (size_t)(t * B + b) * H + tid] = hn;
    }
    __syncthreads();                               // (B)

    // reload column registers (new h / te) + own-row scalars
    float h_r0, h_r1, te_r0, te_r1;
    {
      const float4* h4 = (const float4*)S->h;
      const float4* t4 = (const float4*)S->te;
      float4 a = h4[lane], c = h4[32 + lane];
      hreg[0]=a.x; hreg[1]=a.y; hreg[2]=a.z; hreg[3]=a.w;
      hreg[4]=c.x; hreg[5]=c.y; hreg[6]=c.z; hreg[7]=c.w;
      a = t4[lane]; c = t4[32 + lane];
      tereg[0]=a.x; tereg[1]=a.y; tereg[2]=a.z; tereg[3]=a.w;
      tereg[4]=c.x; tereg[5]=c.y; tereg[6]=c.z; tereg[7]=c.w;
      h_r0 = S->h[gi0]; h_r1 = S->h[gi0 + 1];
      te_r0 = S->te[gi0]; te_r1 = S->te[gi0 + 1];
    }

    // ---- F: mod = relu(h_new @ Wm^T + b), 2 rows/warp + scalar partials ----
    {
      float m0 = dot4(Wm4[(wid * 2) * 64 + lane], hreg)
               + dot4(Wm4[(wid * 2) * 64 + 32 + lane], hreg + 4);
      float m1 = dot4(Wm4[(wid * 2 + 1) * 64 + lane], hreg)
               + dot4(Wm4[(wid * 2 + 1) * 64 + 32 + lane], hreg + 4);
      float a = (lane & 16) ? m1 : m0;
      float c = (lane & 16) ? m0 : m1;
      float vsum = a + __shfl_xor_sync(~0u, c, 16);
#pragma unroll
      for (int o = 8; o; o >>= 1) vsum += __shfl_xor_sync(~0u, vsum, o);
      float mval  = fmaxf(vsum + bhm_l, 0.f);          // row (2wid + lane>>4)
      float other = __shfl_xor_sync(~0u, mval, 16);
      if (lane == 0) {
        // lane 0 holds row 2wid, other = row 2wid+1
        S->modred[wid] = make_float2(wsA * mval + wsB * other,
                                     wmA * mval + wmB * other);
      }
      if ((lane & 15) == 0) S->mod[mrow] = mval;
    }
    __syncthreads();                               // (C)

    // ---- s, m from modred (4-stage butterfly over 16 entries) ----
    float2 mr = S->modred[lane & 15];
    float t0 = mr.x, t1 = mr.y;
#pragma unroll
    for (int o = 8; o; o >>= 1) {
      t0 += __shfl_xor_sync(~0u, t0, o);
      t1 += __shfl_xor_sync(~0u, t1, o);
    }
    float s = sigm(t0 + bm0);
    float m = t1 + bm1;
    if (rank == 0 && tid < R)
      out[MODS_OFF + (size_t)(t * B + b) * R + tid] = S->mod[tid];

    // ---- G: dU / tE update + clip + next-step plastic partials ----
    pp0 = 0.f; pp1 = 0.f;
#pragma unroll
    for (int j = 0; j < 8; ++j) {
      {
        float outer = h_r0 * tereg[j] - te_r0 * hreg[j];
        float E = tEr[0][j] + s * (outer - tEr[0][j]);
        tEr[0][j] = E;
        float d = dUr[0][j] + tau * (m * E - dUr[0][j]);
        d = fminf(fmaxf(d, lor[0][j]), upr[0][j]);
        dUr[0][j] = d;
        pp0 += d * hreg[j];
      }
      {
        float outer = h_r1 * tereg[j] - te_r1 * hreg[j];
        float E = tEr[1][j] + s * (outer - tEr[1][j]);
        tEr[1][j] = E;
        float d = dUr[1][j] + tau * (m * E - dUr[1][j]);
        d = fminf(fmaxf(d, lor[1][j]), upr[1][j]);
        dUr[1][j] = d;
        pp1 += d * hreg[j];
      }
    }
  }

  // ================= epilogue ===============================================
  if (rank == 0 && tid < 256) {
    out[V_OFF  + b * H + tid] = v_own;
    out[H_OFF  + b * H + tid] = h_own;
    out[TE_OFF + b * H + tid] = te_own;
  }
#pragma unroll
  for (int rr = 0; rr < 2; ++rr) {
    int gi = gi0 + rr;
    size_t rb = ((size_t)b * H + gi) * H;
    float4 a, c;
    a.x=dUr[rr][0]; a.y=dUr[rr][1]; a.z=dUr[rr][2]; a.w=dUr[rr][3];
    c.x=dUr[rr][4]; c.y=dUr[rr][5]; c.z=dUr[rr][6]; c.w=dUr[rr][7];
    ((float4*)(out + DU_OFF + rb))[lane]      = a;
    ((float4*)(out + DU_OFF + rb))[32 + lane] = c;
    a.x=tEr[rr][0]; a.y=tEr[rr][1]; a.z=tEr[rr][2]; a.w=tEr[rr][3];
    c.x=tEr[rr][4]; c.y=tEr[rr][5]; c.z=tEr[rr][6]; c.w=tEr[rr][7];
    ((float4*)(out + TEE_OFF + rb))[lane]      = a;
    ((float4*)(out + TEE_OFF + rb))[32 + lane] = c;
  }
}

extern "C" void kernel_launch(void* const* d_in, const int* in_sizes, int n_in,
                              void* d_out, int out_size) {
  (void)in_sizes; (void)n_in; (void)out_size;
  const float* x_in   = (const float*)d_in[0];
  const float* h0     = (const float*)d_in[1];
  const float* v0     = (const float*)d_in[2];
  const float* dU0    = (const float*)d_in[3];
  const float* te0    = (const float*)d_in[4];
  const float* tE0    = (const float*)d_in[5];
  const float* Wx2h   = (const float*)d_in[6];
  const float* bx2h   = (const float*)d_in[7];
  const float* Wh2h   = (const float*)d_in[8];
  const float* bh2h   = (const float*)d_in[9];
  const float* lnxg   = (const float*)d_in[10];
  const float* lnxb   = (const float*)d_in[11];
  const float* lnhg   = (const float*)d_in[12];
  const float* lnhb   = (const float*)d_in[13];
  const float* Wh2mod = (const float*)d_in[14];
  const float* bh2mod = (const float*)d_in[15];
  const float* Wmod2h = (const float*)d_in[16];
  const float* bmod2h = (const float*)d_in[17];
  const float* alpha  = (const float*)d_in[18];
  const float* tauU   = (const float*)d_in[19];
  float* out = (float*)d_out;

  cudaFuncSetAttribute(sgru_persistent,
                       cudaFuncAttributeMaxDynamicSharedMemorySize,
                       (int)sizeof(SM));
  sgru_persistent<<<B * 8, 512, sizeof(SM)>>>(
      x_in, h0, v0, dU0, te0, tE0, Wx2h, bx2h, Wh2h, bh2h,
      lnxg, lnxb, lnhg, lnhb, Wh2mod, bh2mod, Wmod2h, bmod2h,
      alpha, tauU, out);
}

// round 5
// speedup vs baseline: 2.3618x; 1.0556x over previous
#include <cuda_runtime.h>
#include <math.h>
#include <stdint.h>

namespace {
constexpr int H  = 256;
constexpr int I  = 128;
constexpr int R  = 32;
constexpr int B  = 16;
constexpr int T  = 48;
constexpr int H3 = 768;

constexpr long V_OFF    = 0;
constexpr long H_OFF    = V_OFF  + (long)B * H;
constexpr long DU_OFF   = H_OFF  + (long)B * H;
constexpr long TE_OFF   = DU_OFF + (long)B * H * H;
constexpr long TEE_OFF  = TE_OFF + (long)B * H;
constexpr long OUTS_OFF = TEE_OFF + (long)B * H * H;
constexpr long MODS_OFF = OUTS_OFF + (long)T * B * H;

constexpr unsigned EXPECT_BYTES = 4096;  // 8 peers * 16 warps * 4 lanes * 8B
}

__device__ float g_Wx[(size_t)T * B * H3];   // LN(x @ Wx2h^T + b), prologue

struct SM {
  float Ws[96 * 256];      // W_h2h slice, reordered: [0:32)=z, [32:64)=r, [64:96)=dv rows
  float Wm[32 * 256];      // W_h2mod
  float  whx[2][H3];       // st.async-exchanged pre-LN vector (bias+plastic included)
  float2 stats[2][128];    // st.async-exchanged per-warp (sum, sumsq) partials
  float h[H];
  float te[H];
  float mod[R];
  float2 modred[16];       // per-warp (t0,t1) partials for s/m
  float2 red[16];          // prologue LN
  unsigned long long mbar[2];  // double-buffered tx barriers
};

__device__ __forceinline__ float sigm(float x) { return 1.0f / (1.0f + __expf(-x)); }

__device__ __forceinline__ void cluster_sync_() {
  asm volatile("barrier.cluster.arrive.aligned;\n\tbarrier.cluster.wait.aligned;" ::: "memory");
}

__device__ __forceinline__ uint32_t smem_u32(const void* p) {
  return (uint32_t)__cvta_generic_to_shared(p);
}

__device__ __forceinline__ uint32_t mapa_u32(uint32_t addr, uint32_t peer) {
  uint32_t r;
  asm("mapa.shared::cluster.u32 %0, %1, %2;" : "=r"(r) : "r"(addr), "r"(peer));
  return r;
}

// remote store with transaction completion on the CONSUMER's mbarrier
__device__ __forceinline__ void st_async_2f(uint32_t raddr, float a, float b, uint32_t rmbar) {
  unsigned long long pk = (unsigned long long)__float_as_uint(a) |
                          ((unsigned long long)__float_as_uint(b) << 32);
  asm volatile("st.async.shared::cluster.mbarrier::complete_tx::bytes.b64 [%0], %1, [%2];"
               :: "r"(raddr), "l"(pk), "r"(rmbar) : "memory");
}

__device__ __forceinline__ void mbar_arm(uint32_t mbar, uint32_t bytes) {
  asm volatile("mbarrier.arrive.expect_tx.shared.b64 _, [%0], %1;"
               :: "r"(mbar), "r"(bytes) : "memory");
}

__device__ __forceinline__ void mbar_init(uint32_t mbar, uint32_t count) {
  asm volatile("mbarrier.init.shared.b64 [%0], %1;" :: "r"(mbar), "r"(count) : "memory");
}

__device__ __forceinline__ void mbar_wait(uint32_t mbar, uint32_t parity) {
  uint32_t done;
  asm volatile("{\n\t.reg .pred p;\n\t"
               "mbarrier.try_wait.parity.acquire.cta.shared::cta.b64 p, [%1], %2;\n\t"
               "selp.b32 %0, 1, 0, p;\n\t}"
               : "=r"(done) : "r"(mbar), "r"(parity) : "memory");
  while (!done) {
    asm volatile("{\n\t.reg .pred p;\n\t"
                 "mbarrier.try_wait.parity.acquire.cta.shared::cta.b64 p, [%1], %2, 0x989680;\n\t"
                 "selp.b32 %0, 1, 0, p;\n\t}"
                 : "=r"(done) : "r"(mbar), "r"(parity) : "memory");
  }
}

__device__ __forceinline__ float dot4(float4 a, const float* h) {
  return a.x * h[0] + a.y * h[1] + a.z * h[2] + a.w * h[3];
}

__global__ void __cluster_dims__(8, 1, 1) __launch_bounds__(512, 1)
sgru_persistent(const float* __restrict__ x_in,
                const float* __restrict__ h0,
                const float* __restrict__ v0,
                const float* __restrict__ dU0,
                const float* __restrict__ te0,
                const float* __restrict__ tE0,
                const float* __restrict__ Wx2h,
                const float* __restrict__ bx2h,
                const float* __restrict__ Wh2h,
                const float* __restrict__ bh2h,
                const float* __restrict__ lnxg,
                const float* __restrict__ lnxb,
                const float* __restrict__ lnhg,
                const float* __restrict__ lnhb,
                const float* __restrict__ Wh2mod,
                const float* __restrict__ bh2mod,
                const float* __restrict__ Wmod2h,
                const float* __restrict__ bmod2h,
                const float* __restrict__ alpha,
                const float* __restrict__ tauU,
                float* __restrict__ out)
{
  extern __shared__ unsigned char smem_raw[];
  SM* S = reinterpret_cast<SM*>(smem_raw);
  const int tid  = threadIdx.x;
  const int wid  = tid >> 5;
  const int lane = tid & 31;
  const int rank = blockIdx.x & 7;
  const int b    = blockIdx.x >> 3;
  const int gi0  = 32 * rank + 2 * wid;   // this warp's slot base (2 slots)

  const float a0      = alpha[0];
  const float sp_a    = (a0 > 0.f) ? (a0 + log1pf(expf(-a0))) : log1pf(expf(a0));
  const float inv_spa = 1.0f / sp_a;
  const float tau     = sigm(tauU[0]);
  const float bm0     = bmod2h[0];
  const float bm1     = bmod2h[1];

  // ================= prologue: Wx = x @ Wx2h^T + b (raw) =====================
  {
    const float4* WxA = (const float4*)(Wx2h + (size_t)96 * rank * I);
    float4* Ws4w = (float4*)S->Ws;
    for (int i = tid; i < 96 * I / 4; i += 512) Ws4w[i] = WxA[i];
  }
  __syncthreads();
  {
    const float4* Ws4c = (const float4*)S->Ws;
    for (int it = 0; it < 3; ++it) {
      int t = wid + 16 * it;
      float4 x4 = ((const float4*)x_in)[(size_t)(t * B + b) * 32 + lane];
      for (int g = 0; g < 6; ++g) {
        float acc[16];
#pragma unroll
        for (int k = 0; k < 16; ++k) {
          float4 w = Ws4c[(g * 16 + k) * 32 + lane];
          acc[k] = w.x * x4.x + w.y * x4.y + w.z * x4.z + w.w * x4.w;
        }
#pragma unroll
        for (int k = 0; k < 8; ++k) {
          float a = (lane & 16) ? acc[k + 8] : acc[k];
          float c = (lane & 16) ? acc[k] : acc[k + 8];
          acc[k] = a + __shfl_xor_sync(~0u, c, 16);
        }
#pragma unroll
        for (int k = 0; k < 4; ++k) {
          float a = (lane & 8) ? acc[k + 4] : acc[k];
          float c = (lane & 8) ? acc[k] : acc[k + 4];
          acc[k] = a + __shfl_xor_sync(~0u, c, 8);
        }
#pragma unroll
        for (int k = 0; k < 2; ++k) {
          float a = (lane & 4) ? acc[k + 2] : acc[k];
          float c = (lane & 4) ? acc[k] : acc[k + 2];
          acc[k] = a + __shfl_xor_sync(~0u, c, 4);
        }
#pragma unroll
        for (int o = 2; o; o >>= 1) {
          acc[0] += __shfl_xor_sync(~0u, acc[0], o);
          acc[1] += __shfl_xor_sync(~0u, acc[1], o);
        }
        if ((lane & 3) == 0) {
          int p = (lane >> 2) & 7;
          int o = 96 * rank + g * 16 + 2 * p;
          float2 bias = *(const float2*)&bx2h[o];
          float2 val = make_float2(acc[0] + bias.x, acc[1] + bias.y);
          *(float2*)&g_Wx[(size_t)(t * B + b) * H3 + o] = val;
        }
      }
    }
  }
  cluster_sync_();

  // ================= prologue LN over g_Wx ===================================
  for (int t = rank; t < T; t += 8) {
    float* base = &g_Wx[(size_t)(t * B + b) * H3];
    float e0 = base[tid];
    float e1 = (tid < 256) ? base[512 + tid] : 0.f;
    float s1 = e0 + e1, s2 = e0 * e0 + e1 * e1;
#pragma unroll
    for (int o = 16; o; o >>= 1) {
      s1 += __shfl_xor_sync(~0u, s1, o);
      s2 += __shfl_xor_sync(~0u, s2, o);
    }
    if (lane == 0) S->red[wid] = make_float2(s1, s2);
    __syncthreads();
    float ssum = 0.f, ssq = 0.f;
#pragma unroll
    for (int i = 0; i < 16; ++i) { float2 rr = S->red[i]; ssum += rr.x; ssq += rr.y; }
    float mu   = ssum * (1.0f / H3);
    float var  = ssq * (1.0f / H3) - mu * mu;
    float rstd = rsqrtf(var + 1e-5f);
    base[tid] = (e0 - mu) * rstd * lnxg[tid] + lnxb[tid];
    if (tid < 256)
      base[512 + tid] = (e1 - mu) * rstd * lnxg[512 + tid] + lnxb[512 + tid];
    __syncthreads();
  }

  // ================= load main-loop smem + register state ===================
  {
    // Ws reordered: local row q -> global row (q>>5)*256 + 32*rank + (q&31)
    float4* Ws4w = (float4*)S->Ws;
    for (int i = tid; i < 96 * 64; i += 512) {
      int q = i >> 6, c4 = i & 63;
      int grow = ((q >> 5) << 8) + 32 * rank + (q & 31);
      Ws4w[i] = ((const float4*)(Wh2h + (size_t)grow * H))[c4];
    }
    const float4* Wm4s = (const float4*)Wh2mod;
    float4* Wm4w = (float4*)S->Wm;
    for (int i = tid; i < 32 * 64; i += 512) Wm4w[i] = Wm4s[i];
  }
  float h_own = 0.f, v_own = 0.f, te_own = 0.f;
  float g0 = 0.f, g1 = 0.f, g2 = 0.f, lb0 = 0.f, lb1 = 0.f, lb2 = 0.f;
  if (tid < 256) {
    h_own  = h0[b * H + tid];
    v_own  = v0[b * H + tid];
    te_own = te0[b * H + tid];
    S->h[tid]  = h_own;
    S->te[tid] = te_own;
    g0 = lnhg[tid]; g1 = lnhg[tid + 256]; g2 = lnhg[tid + 512];
    lb0 = lnhb[tid]; lb1 = lnhb[tid + 256]; lb2 = lnhb[tid + 512];
  }

  // tx barriers: init + arm for first use of each buffer
  const uint32_t mb_local = smem_u32(&S->mbar[0]);
  if (tid == 0) {
    mbar_init(mb_local, 1);
    mbar_init(mb_local + 8, 1);
    mbar_arm(mb_local, EXPECT_BYTES);
    mbar_arm(mb_local + 8, EXPECT_BYTES);
  }

  // per-lane fold pair p and preloaded bias pair
  const int pgrp = (lane >> 3) & 3;
  float pb0 = 0.f, pb1 = 0.f;
  if (pgrp < 3) {
    pb0 = bh2h[256 * pgrp + gi0];
    pb1 = bh2h[256 * pgrp + gi0 + 1];
  }
  // preloaded s/m weights (warp-uniform) and mod bias (per half-warp)
  const float wsA = Wmod2h[2 * wid], wsB = Wmod2h[2 * wid + 1];
  const float wmA = Wmod2h[R + 2 * wid], wmB = Wmod2h[R + 2 * wid + 1];
  const int   mrow = 2 * wid + ((lane >> 4) & 1);
  const float bhm_l = bh2mod[mrow];

  // dU / tE rows gi0, gi0+1 ; cols {4*lane..+3, 128+4*lane..+3}
  float dUr[2][8], tEr[2][8], upr[2][8], lor[2][8];
#pragma unroll
  for (int rr = 0; rr < 2; ++rr) {
    int gi = gi0 + rr;
    const float4* du4 = (const float4*)(dU0 + ((size_t)b * H + gi) * H);
    const float4* tE4 = (const float4*)(tE0 + ((size_t)b * H + gi) * H);
    const float4* wv4 = (const float4*)(Wh2h + (size_t)(512 + gi) * H);
    float4 a, c;
    a = du4[lane]; c = du4[32 + lane];
    dUr[rr][0]=a.x; dUr[rr][1]=a.y; dUr[rr][2]=a.z; dUr[rr][3]=a.w;
    dUr[rr][4]=c.x; dUr[rr][5]=c.y; dUr[rr][6]=c.z; dUr[rr][7]=c.w;
    a = tE4[lane]; c = tE4[32 + lane];
    tEr[rr][0]=a.x; tEr[rr][1]=a.y; tEr[rr][2]=a.z; tEr[rr][3]=a.w;
    tEr[rr][4]=c.x; tEr[rr][5]=c.y; tEr[rr][6]=c.z; tEr[rr][7]=c.w;
    a = wv4[lane]; c = wv4[32 + lane];
    float wv[8] = {a.x,a.y,a.z,a.w,c.x,c.y,c.z,c.w};
#pragma unroll
    for (int j = 0; j < 8; ++j) {
      upr[rr][j] =  fmaxf(1.f - wv[j], 0.f) * inv_spa;
      lor[rr][j] = -fmaxf(1.f + wv[j], 0.f) * inv_spa;
    }
  }

  const uint32_t whx_peer   = mapa_u32(smem_u32(&S->whx[0][0]),   lane & 7);
  const uint32_t stats_peer = mapa_u32(smem_u32(&S->stats[0][0]), lane & 7);
  const uint32_t mbar_peer  = mapa_u32(mb_local,                  lane & 7);

  // orders mbarrier init + smem state cluster-wide before any st.async lands
  cluster_sync_();

  float hreg[8], tereg[8];
  {
    const float4* h4 = (const float4*)S->h;
    const float4* t4 = (const float4*)S->te;
    float4 a = h4[lane], c = h4[32 + lane];
    hreg[0]=a.x; hreg[1]=a.y; hreg[2]=a.z; hreg[3]=a.w;
    hreg[4]=c.x; hreg[5]=c.y; hreg[6]=c.z; hreg[7]=c.w;
    a = t4[lane]; c = t4[32 + lane];
    tereg[0]=a.x; tereg[1]=a.y; tereg[2]=a.z; tereg[3]=a.w;
    tereg[4]=c.x; tereg[5]=c.y; tereg[6]=c.z; tereg[7]=c.w;
  }

  // initial plastic partials: dU0 . h0 (per-lane partial over owned cols)
  float pp0 = 0.f, pp1 = 0.f;
#pragma unroll
  for (int j = 0; j < 8; ++j) { pp0 += dUr[0][j] * hreg[j]; pp1 += dUr[1][j] * hreg[j]; }

  const float4* Ws4 = (const float4*)S->Ws;
  const float4* Wm4 = (const float4*)S->Wm;

  // ================= main scan ==============================================
  int par = 0;
  for (int t = 0; t < T; ++t, par ^= 1) {
    const uint32_t use_parity = (uint32_t)(t >> 1) & 1u;

    // prefetch x-projection for phase 2 (issued first, consumed after wait)
    float wx0 = 0.f, wx1 = 0.f, wx2 = 0.f;
    if (tid < 256) {
      const float* wxp = &g_Wx[(size_t)(t * B + b) * H3];
      wx0 = __ldcg(wxp + tid);
      wx1 = __ldcg(wxp + tid + 256);
      wx2 = __ldcg(wxp + tid + 512);
    }

    // ---- A: GEMV 6 rows (z0,z1,r0,r1,dv0,dv1) + fused plastic ----
    float acc[8];
    acc[0] = dot4(Ws4[(2*wid)    * 64 + lane], hreg) + dot4(Ws4[(2*wid)    * 64 + 32 + lane], hreg + 4);
    acc[1] = dot4(Ws4[(2*wid+1)  * 64 + lane], hreg) + dot4(Ws4[(2*wid+1)  * 64 + 32 + lane], hreg + 4);
    acc[2] = dot4(Ws4[(32+2*wid) * 64 + lane], hreg) + dot4(Ws4[(32+2*wid) * 64 + 32 + lane], hreg + 4);
    acc[3] = dot4(Ws4[(33+2*wid) * 64 + lane], hreg) + dot4(Ws4[(33+2*wid) * 64 + 32 + lane], hreg + 4);
    acc[4] = dot4(Ws4[(64+2*wid) * 64 + lane], hreg) + dot4(Ws4[(64+2*wid) * 64 + 32 + lane], hreg + 4)
             + sp_a * pp0;
    acc[5] = dot4(Ws4[(65+2*wid) * 64 + lane], hreg) + dot4(Ws4[(65+2*wid) * 64 + 32 + lane], hreg + 4)
             + sp_a * pp1;
    acc[6] = 0.f; acc[7] = 0.f;

    // ---- fold 8 -> 2 ----
#pragma unroll
    for (int k = 0; k < 4; ++k) {
      float a = (lane & 16) ? acc[k + 4] : acc[k];
      float c = (lane & 16) ? acc[k] : acc[k + 4];
      acc[k] = a + __shfl_xor_sync(~0u, c, 16);
    }
#pragma unroll
    for (int k = 0; k < 2; ++k) {
      float a = (lane & 8) ? acc[k + 2] : acc[k];
      float c = (lane & 8) ? acc[k] : acc[k + 2];
      acc[k] = a + __shfl_xor_sync(~0u, c, 8);
    }
#pragma unroll
    for (int o = 4; o; o >>= 1) {
      acc[0] += __shfl_xor_sync(~0u, acc[0], o);
      acc[1] += __shfl_xor_sync(~0u, acc[1], o);
    }
    // bias + warp stats (sum, sumsq over this warp's 6 values)
    acc[0] += pb0; acc[1] += pb1;                 // pb=0 for pgrp==3 (zero slots)
    float u = acc[0] + acc[1];
    float q = acc[0] * acc[0] + acc[1] * acc[1];
    u += __shfl_xor_sync(~0u, u, 8);  q += __shfl_xor_sync(~0u, q, 8);
    u += __shfl_xor_sync(~0u, u, 16); q += __shfl_xor_sync(~0u, q, 16);

    // ---- st.async with tx-completion on peer's mbarrier ----
    {
      const uint32_t rmbar = mbar_peer + 8u * (uint32_t)par;
      if (pgrp < 3) {
        st_async_2f(whx_peer + (uint32_t)(par * H3 + 256 * pgrp + gi0) * 4u,
                    acc[0], acc[1], rmbar);
      } else {
        st_async_2f(stats_peer + (uint32_t)(par * 128 + rank * 16 + wid) * 8u,
                    u, q, rmbar);
      }
    }

    // ---- wait for all 4096 bytes (warps 0-7 only), re-arm for t+2 ----
    if (wid < 8) {
      mbar_wait(mb_local + 8u * (uint32_t)par, use_parity);
      if (tid == 0) mbar_arm(mb_local + 8u * (uint32_t)par, EXPECT_BYTES);
    }

    // ---- D: stats combine (no barrier) + phase 2 ----
    if (tid < 256) {
      const float4* st4 = (const float4*)&S->stats[par][0];
      float4 A = st4[lane], Bv = st4[32 + lane];
      float su = A.x + A.z + Bv.x + Bv.z;
      float sq = A.y + A.w + Bv.y + Bv.w;
#pragma unroll
      for (int o = 16; o; o >>= 1) {
        su += __shfl_xor_sync(~0u, su, o);
        sq += __shfl_xor_sync(~0u, sq, o);
      }
      float mu   = su * (1.0f / H3);
      float var  = sq * (1.0f / H3) - mu * mu;
      float rstd = rsqrtf(var + 1e-5f);

      float w0 = S->whx[par][tid];
      float w1 = S->whx[par][256 + tid];
      float w2 = S->whx[par][512 + tid];
      float pre0 = (w0 - mu) * rstd * g0 + lb0 + wx0;
      float pre1 = (w1 - mu) * rstd * g1 + lb1 + wx1;
      float pre2 = (w2 - mu) * rstd * g2 + lb2 + wx2;
      float z  = sigm(pre0);
      float r  = sigm(pre1);
      float vn = v_own + z * (pre2 - v_own);
      float hn = fmaxf(vn, 0.f);
      float tn = te_own + r * (h_own - te_own);   // OLD h
      v_own = vn; h_own = hn; te_own = tn;
      S->h[tid]  = hn;
      S->te[tid] = tn;
      if (rank == 0) out[OUTS_OFF + (size_t)(t * B + b) * H + tid] = hn;
    }
    __syncthreads();                               // (B)

    // reload column registers (new h / te) + own-row scalars
    float h_r0, h_r1, te_r0, te_r1;
    {
      const float4* h4 = (const float4*)S->h;
      const float4* t4 = (const float4*)S->te;
      float4 a = h4[lane], c = h4[32 + lane];
      hreg[0]=a.x; hreg[1]=a.y; hreg[2]=a.z; hreg[3]=a.w;
      hreg[4]=c.x; hreg[5]=c.y; hreg[6]=c.z; hreg[7]=c.w;
      a = t4[lane]; c = t4[32 + lane];
      tereg[0]=a.x; tereg[1]=a.y; tereg[2]=a.z; tereg[3]=a.w;
      tereg[4]=c.x; tereg[5]=c.y; tereg[6]=c.z; tereg[7]=c.w;
      h_r0 = S->h[gi0]; h_r1 = S->h[gi0 + 1];
      te_r0 = S->te[gi0]; te_r1 = S->te[gi0 + 1];
    }

    // ---- F: mod = relu(h_new @ Wm^T + b), 2 rows/warp + scalar partials ----
    {
      float m0 = dot4(Wm4[(wid * 2) * 64 + lane], hreg)
               + dot4(Wm4[(wid * 2) * 64 + 32 + lane], hreg + 4);
      float m1 = dot4(Wm4[(wid * 2 + 1) * 64 + lane], hreg)
               + dot4(Wm4[(wid * 2 + 1) * 64 + 32 + lane], hreg + 4);
      float a = (lane & 16) ? m1 : m0;
      float c = (lane & 16) ? m0 : m1;
      float vsum = a + __shfl_xor_sync(~0u, c, 16);
#pragma unroll
      for (int o = 8; o; o >>= 1) vsum += __shfl_xor_sync(~0u, vsum, o);
      float mval  = fmaxf(vsum + bhm_l, 0.f);          // row (2wid + lane>>4)
      float other = __shfl_xor_sync(~0u, mval, 16);
      if (lane == 0) {
        // lane 0 holds row 2wid, other = row 2wid+1
        S->modred[wid] = make_float2(wsA * mval + wsB * other,
                                     wmA * mval + wmB * other);
      }
      if ((lane & 15) == 0) S->mod[mrow] = mval;
    }
    __syncthreads();                               // (C)

    // ---- s, m from modred ----
    float2 mr = S->modred[lane & 15];
    float t0 = mr.x, t1 = mr.y;
#pragma unroll
    for (int o = 8; o; o >>= 1) {
      t0 += __shfl_xor_sync(~0u, t0, o);
      t1 += __shfl_xor_sync(~0u, t1, o);
    }
    float s = sigm(t0 + bm0);
    float m = t1 + bm1;
    if (rank == 0 && tid < R)
      out[MODS_OFF + (size_t)(t * B + b) * R + tid] = S->mod[tid];

    // ---- G: dU / tE update + clip + next-step plastic partials ----
    pp0 = 0.f; pp1 = 0.f;
#pragma unroll
    for (int j = 0; j < 8; ++j) {
      {
        float outer = h_r0 * tereg[j] - te_r0 * hreg[j];
        float E = tEr[0][j] + s * (outer - tEr[0][j]);
        tEr[0][j] = E;
        float d = dUr[0][j] + tau * (m * E - dUr[0][j]);
        d = fminf(fmaxf(d, lor[0][j]), upr[0][j]);
        dUr[0][j] = d;
        pp0 += d * hreg[j];
      }
      {
        float outer = h_r1 * tereg[j] - te_r1 * hreg[j];
        float E = tEr[1][j] + s * (outer - tEr[1][j]);
        tEr[1][j] = E;
        float d = dUr[1][j] + tau * (m * E - dUr[1][j]);
        d = fminf(fmaxf(d, lor[1][j]), upr[1][j]);
        dUr[1][j] = d;
        pp1 += d * hreg[j];
      }
    }
  }

  // ================= epilogue ===============================================
  if (rank == 0 && tid < 256) {
    out[V_OFF  + b * H + tid] = v_own;
    out[H_OFF  + b * H + tid] = h_own;
    out[TE_OFF + b * H + tid] = te_own;
  }
#pragma unroll
  for (int rr = 0; rr < 2; ++rr) {
    int gi = gi0 + rr;
    size_t rb = ((size_t)b * H + gi) * H;
    float4 a, c;
    a.x=dUr[rr][0]; a.y=dUr[rr][1]; a.z=dUr[rr][2]; a.w=dUr[rr][3];
    c.x=dUr[rr][4]; c.y=dUr[rr][5]; c.z=dUr[rr][6]; c.w=dUr[rr][7];
    ((float4*)(out + DU_OFF + rb))[lane]      = a;
    ((float4*)(out + DU_OFF + rb))[32 + lane] = c;
    a.x=tEr[rr][0]; a.y=tEr[rr][1]; a.z=tEr[rr][2]; a.w=tEr[rr][3];
    c.x=tEr[rr][4]; c.y=tEr[rr][5]; c.z=tEr[rr][6]; c.w=tEr[rr][7];
    ((float4*)(out + TEE_OFF + rb))[lane]      = a;
    ((float4*)(out + TEE_OFF + rb))[32 + lane] = c;
  }
}

extern "C" void kernel_launch(void* const* d_in, const int* in_sizes, int n_in,
                              void* d_out, int out_size) {
  (void)in_sizes; (void)n_in; (void)out_size;
  const float* x_in   = (const float*)d_in[0];
  const float* h0     = (const float*)d_in[1];
  const float* v0     = (const float*)d_in[2];
  const float* dU0    = (const float*)d_in[3];
  const float* te0    = (const float*)d_in[4];
  const float* tE0    = (const float*)d_in[5];
  const float* Wx2h   = (const float*)d_in[6];
  const float* bx2h   = (const float*)d_in[7];
  const float* Wh2h   = (const float*)d_in[8];
  const float* bh2h   = (const float*)d_in[9];
  const float* lnxg   = (const float*)d_in[10];
  const float* lnxb   = (const float*)d_in[11];
  const float* lnhg   = (const float*)d_in[12];
  const float* lnhb   = (const float*)d_in[13];
  const float* Wh2mod = (const float*)d_in[14];
  const float* bh2mod = (const float*)d_in[15];
  const float* Wmod2h = (const float*)d_in[16];
  const float* bmod2h = (const float*)d_in[17];
  const float* alpha  = (const float*)d_in[18];
  const float* tauU   = (const float*)d_in[19];
  float* out = (float*)d_out;

  cudaFuncSetAttribute(sgru_persistent,
                       cudaFuncAttributeMaxDynamicSharedMemorySize,
                       (int)sizeof(SM));
  sgru_persistent<<<B * 8, 512, sizeof(SM)>>>(
      x_in, h0, v0, dU0, te0, tE0, Wx2h, bx2h, Wh2h, bh2h,
      lnxg, lnxb, lnhg, lnhb, Wh2mod, bh2mod, Wmod2h, bmod2h,
      alpha, tauU, out);
}

// round 6
// speedup vs baseline: 2.3762x; 1.0061x over previous
#include <cuda_runtime.h>
#include <math.h>
#include <stdint.h>
#include <cstdio>

namespace {
constexpr int H  = 256;
constexpr int I  = 128;
constexpr int R  = 32;
constexpr int B  = 16;
constexpr int T  = 48;
constexpr int H3 = 768;

constexpr long V_OFF    = 0;
constexpr long H_OFF    = V_OFF  + (long)B * H;
constexpr long DU_OFF   = H_OFF  + (long)B * H;
constexpr long TE_OFF   = DU_OFF + (long)B * H * H;
constexpr long TEE_OFF  = TE_OFF + (long)B * H;
constexpr long OUTS_OFF = TEE_OFF + (long)B * H * H;
constexpr long MODS_OFF = OUTS_OFF + (long)T * B * H;

constexpr unsigned EXPECT_BYTES = 4096;  // 8 peers * 16 warps * 4 lanes * 8B
}

__device__ float g_Wx[(size_t)T * B * H3];   // LN(x @ Wx2h^T + b), prologue

struct SM {
  float Ws[96 * 256];      // W_h2h slice, reordered: [0:32)=z, [32:64)=r, [64:96)=dv rows
  float Wm[32 * 256];      // W_h2mod
  float  whx[2][H3];       // st.async-exchanged pre-LN vector (bias+plastic included)
  float2 stats[2][128];    // st.async-exchanged per-warp (sum, sumsq) partials
  float4 bndU[2][2][512];  // clip upper bounds, SoA [rr][chunk][tid]
  float4 bndL[2][2][512];  // clip lower bounds
  float h[H];
  float te[H];
  float mod[R];
  float2 modred[16];       // per-warp (t0,t1) partials for s/m
  float2 red[16];          // prologue LN
  unsigned long long mbar[2];  // double-buffered tx barriers
};

__device__ __forceinline__ float sigm(float x) { return 1.0f / (1.0f + __expf(-x)); }

__device__ __forceinline__ void cluster_sync_() {
  asm volatile("barrier.cluster.arrive.aligned;\n\tbarrier.cluster.wait.aligned;" ::: "memory");
}

__device__ __forceinline__ uint32_t smem_u32(const void* p) {
  return (uint32_t)__cvta_generic_to_shared(p);
}

__device__ __forceinline__ uint32_t mapa_u32(uint32_t addr, uint32_t peer) {
  uint32_t r;
  asm("mapa.shared::cluster.u32 %0, %1, %2;" : "=r"(r) : "r"(addr), "r"(peer));
  return r;
}

__device__ __forceinline__ void st_async_2f(uint32_t raddr, float a, float b, uint32_t rmbar) {
  unsigned long long pk = (unsigned long long)__float_as_uint(a) |
                          ((unsigned long long)__float_as_uint(b) << 32);
  asm volatile("st.async.shared::cluster.mbarrier::complete_tx::bytes.b64 [%0], %1, [%2];"
               :: "r"(raddr), "l"(pk), "r"(rmbar) : "memory");
}

__device__ __forceinline__ void mbar_arm(uint32_t mbar, uint32_t bytes) {
  asm volatile("mbarrier.arrive.expect_tx.shared.b64 _, [%0], %1;"
               :: "r"(mbar), "r"(bytes) : "memory");
}

__device__ __forceinline__ void mbar_init(uint32_t mbar, uint32_t count) {
  asm volatile("mbarrier.init.shared.b64 [%0], %1;" :: "r"(mbar), "r"(count) : "memory");
}

__device__ __forceinline__ void mbar_wait(uint32_t mbar, uint32_t parity) {
  uint32_t done;
  asm volatile("{\n\t.reg .pred p;\n\t"
               "mbarrier.try_wait.parity.acquire.cta.shared::cta.b64 p, [%1], %2;\n\t"
               "selp.b32 %0, 1, 0, p;\n\t}"
               : "=r"(done) : "r"(mbar), "r"(parity) : "memory");
  while (!done) {
    asm volatile("{\n\t.reg .pred p;\n\t"
                 "mbarrier.try_wait.parity.acquire.cta.shared::cta.b64 p, [%1], %2, 0x989680;\n\t"
                 "selp.b32 %0, 1, 0, p;\n\t}"
                 : "=r"(done) : "r"(mbar), "r"(parity) : "memory");
  }
}

__device__ __forceinline__ float dot4(float4 a, const float* h) {
  return a.x * h[0] + a.y * h[1] + a.z * h[2] + a.w * h[3];
}

__global__ void __cluster_dims__(8, 1, 1) __launch_bounds__(512, 1)
sgru_persistent(const float* __restrict__ x_in,
                const float* __restrict__ h0,
                const float* __restrict__ v0,
                const float* __restrict__ dU0,
                const float* __restrict__ te0,
                const float* __restrict__ tE0,
                const float* __restrict__ Wx2h,
                const float* __restrict__ bx2h,
                const float* __restrict__ Wh2h,
                const float* __restrict__ bh2h,
                const float* __restrict__ lnxg,
                const float* __restrict__ lnxb,
                const float* __restrict__ lnhg,
                const float* __restrict__ lnhb,
                const float* __restrict__ Wh2mod,
                const float* __restrict__ bh2mod,
                const float* __restrict__ Wmod2h,
                const float* __restrict__ bmod2h,
                const float* __restrict__ alpha,
                const float* __restrict__ tauU,
                float* __restrict__ out)
{
  extern __shared__ unsigned char smem_raw[];
  SM* S = reinterpret_cast<SM*>(smem_raw);
  const int tid  = threadIdx.x;
  const int wid  = tid >> 5;
  const int lane = tid & 31;
  const int rank = blockIdx.x & 7;
  const int b    = blockIdx.x >> 3;
  const int gi0  = 32 * rank + 2 * wid;

  const bool iprof = (blockIdx.x == 0 && tid == 0);
  unsigned long long prof[5] = {0, 0, 0, 0, 0};
  long long cp = 0;

  const float a0      = alpha[0];
  const float sp_a    = (a0 > 0.f) ? (a0 + log1pf(expf(-a0))) : log1pf(expf(a0));
  const float inv_spa = 1.0f / sp_a;
  const float tau     = sigm(tauU[0]);
  const float bm0     = bmod2h[0];
  const float bm1     = bmod2h[1];

  // ================= prologue: Wx = x @ Wx2h^T + b (raw) =====================
  {
    const float4* WxA = (const float4*)(Wx2h + (size_t)96 * rank * I);
    float4* Ws4w = (float4*)S->Ws;
    for (int i = tid; i < 96 * I / 4; i += 512) Ws4w[i] = WxA[i];
  }
  __syncthreads();
  {
    const float4* Ws4c = (const float4*)S->Ws;
    for (int it = 0; it < 3; ++it) {
      int t = wid + 16 * it;
      float4 x4 = ((const float4*)x_in)[(size_t)(t * B + b) * 32 + lane];
      for (int g = 0; g < 6; ++g) {
        float acc[16];
#pragma unroll
        for (int k = 0; k < 16; ++k) {
          float4 w = Ws4c[(g * 16 + k) * 32 + lane];
          acc[k] = w.x * x4.x + w.y * x4.y + w.z * x4.z + w.w * x4.w;
        }
#pragma unroll
        for (int k = 0; k < 8; ++k) {
          float a = (lane & 16) ? acc[k + 8] : acc[k];
          float c = (lane & 16) ? acc[k] : acc[k + 8];
          acc[k] = a + __shfl_xor_sync(~0u, c, 16);
        }
#pragma unroll
        for (int k = 0; k < 4; ++k) {
          float a = (lane & 8) ? acc[k + 4] : acc[k];
          float c = (lane & 8) ? acc[k] : acc[k + 4];
          acc[k] = a + __shfl_xor_sync(~0u, c, 8);
        }
#pragma unroll
        for (int k = 0; k < 2; ++k) {
          float a = (lane & 4) ? acc[k + 2] : acc[k];
          float c = (lane & 4) ? acc[k] : acc[k + 2];
          acc[k] = a + __shfl_xor_sync(~0u, c, 4);
        }
#pragma unroll
        for (int o = 2; o; o >>= 1) {
          acc[0] += __shfl_xor_sync(~0u, acc[0], o);
          acc[1] += __shfl_xor_sync(~0u, acc[1], o);
        }
        if ((lane & 3) == 0) {
          int p = (lane >> 2) & 7;
          int o = 96 * rank + g * 16 + 2 * p;
          float2 bias = *(const float2*)&bx2h[o];
          float2 val = make_float2(acc[0] + bias.x, acc[1] + bias.y);
          *(float2*)&g_Wx[(size_t)(t * B + b) * H3 + o] = val;
        }
      }
    }
  }
  cluster_sync_();

  // ================= prologue LN over g_Wx ===================================
  for (int t = rank; t < T; t += 8) {
    float* base = &g_Wx[(size_t)(t * B + b) * H3];
    float e0 = base[tid];
    float e1 = (tid < 256) ? base[512 + tid] : 0.f;
    float s1 = e0 + e1, s2 = e0 * e0 + e1 * e1;
#pragma unroll
    for (int o = 16; o; o >>= 1) {
      s1 += __shfl_xor_sync(~0u, s1, o);
      s2 += __shfl_xor_sync(~0u, s2, o);
    }
    if (lane == 0) S->red[wid] = make_float2(s1, s2);
    __syncthreads();
    float ssum = 0.f, ssq = 0.f;
#pragma unroll
    for (int i = 0; i < 16; ++i) { float2 rr = S->red[i]; ssum += rr.x; ssq += rr.y; }
    float mu   = ssum * (1.0f / H3);
    float var  = ssq * (1.0f / H3) - mu * mu;
    float rstd = rsqrtf(var + 1e-5f);
    base[tid] = (e0 - mu) * rstd * lnxg[tid] + lnxb[tid];
    if (tid < 256)
      base[512 + tid] = (e1 - mu) * rstd * lnxg[512 + tid] + lnxb[512 + tid];
    __syncthreads();
  }

  // ================= load main-loop smem + register state ===================
  {
    float4* Ws4w = (float4*)S->Ws;
    for (int i = tid; i < 96 * 64; i += 512) {
      int q = i >> 6, c4 = i & 63;
      int grow = ((q >> 5) << 8) + 32 * rank + (q & 31);
      Ws4w[i] = ((const float4*)(Wh2h + (size_t)grow * H))[c4];
    }
    const float4* Wm4s = (const float4*)Wh2mod;
    float4* Wm4w = (float4*)S->Wm;
    for (int i = tid; i < 32 * 64; i += 512) Wm4w[i] = Wm4s[i];
  }
  float h_own = 0.f, v_own = 0.f, te_own = 0.f;
  float g0 = 0.f, g1 = 0.f, g2 = 0.f, lb0 = 0.f, lb1 = 0.f, lb2 = 0.f;
  if (tid < 256) {
    h_own  = h0[b * H + tid];
    v_own  = v0[b * H + tid];
    te_own = te0[b * H + tid];
    S->h[tid]  = h_own;
    S->te[tid] = te_own;
    g0 = lnhg[tid]; g1 = lnhg[tid + 256]; g2 = lnhg[tid + 512];
    lb0 = lnhb[tid]; lb1 = lnhb[tid + 256]; lb2 = lnhb[tid + 512];
  }

  const uint32_t mb_local = smem_u32(&S->mbar[0]);
  if (tid == 0) {
    mbar_init(mb_local, 1);
    mbar_init(mb_local + 8, 1);
    mbar_arm(mb_local, EXPECT_BYTES);
    mbar_arm(mb_local + 8, EXPECT_BYTES);
  }

  const int pgrp = (lane >> 3) & 3;
  float pb0 = 0.f, pb1 = 0.f;
  if (pgrp < 3) {
    pb0 = bh2h[256 * pgrp + gi0];
    pb1 = bh2h[256 * pgrp + gi0 + 1];
  }
  const float wsA = Wmod2h[2 * wid], wsB = Wmod2h[2 * wid + 1];
  const float wmA = Wmod2h[R + 2 * wid], wmB = Wmod2h[R + 2 * wid + 1];
  const int   mrow = 2 * wid + ((lane >> 4) & 1);
  const float bhm_l = bh2mod[mrow];

  // dU / tE rows gi0, gi0+1 ; clip bounds go to smem SoA table
  float dUr[2][8], tEr[2][8];
#pragma unroll
  for (int rr = 0; rr < 2; ++rr) {
    int gi = gi0 + rr;
    const float4* du4 = (const float4*)(dU0 + ((size_t)b * H + gi) * H);
    const float4* tE4 = (const float4*)(tE0 + ((size_t)b * H + gi) * H);
    const float4* wv4 = (const float4*)(Wh2h + (size_t)(512 + gi) * H);
    float4 a, c;
    a = du4[lane]; c = du4[32 + lane];
    dUr[rr][0]=a.x; dUr[rr][1]=a.y; dUr[rr][2]=a.z; dUr[rr][3]=a.w;
    dUr[rr][4]=c.x; dUr[rr][5]=c.y; dUr[rr][6]=c.z; dUr[rr][7]=c.w;
    a = tE4[lane]; c = tE4[32 + lane];
    tEr[rr][0]=a.x; tEr[rr][1]=a.y; tEr[rr][2]=a.z; tEr[rr][3]=a.w;
    tEr[rr][4]=c.x; tEr[rr][5]=c.y; tEr[rr][6]=c.z; tEr[rr][7]=c.w;
    a = wv4[lane]; c = wv4[32 + lane];
    float wv[8] = {a.x,a.y,a.z,a.w,c.x,c.y,c.z,c.w};
    float4 u0, u1, l0, l1;
    u0.x =  fmaxf(1.f - wv[0], 0.f) * inv_spa;
    u0.y =  fmaxf(1.f - wv[1], 0.f) * inv_spa;
    u0.z =  fmaxf(1.f - wv[2], 0.f) * inv_spa;
    u0.w =  fmaxf(1.f - wv[3], 0.f) * inv_spa;
    u1.x =  fmaxf(1.f - wv[4], 0.f) * inv_spa;
    u1.y =  fmaxf(1.f - wv[5], 0.f) * inv_spa;
    u1.z =  fmaxf(1.f - wv[6], 0.f) * inv_spa;
    u1.w =  fmaxf(1.f - wv[7], 0.f) * inv_spa;
    l0.x = -fmaxf(1.f + wv[0], 0.f) * inv_spa;
    l0.y = -fmaxf(1.f + wv[1], 0.f) * inv_spa;
    l0.z = -fmaxf(1.f + wv[2], 0.f) * inv_spa;
    l0.w = -fmaxf(1.f + wv[3], 0.f) * inv_spa;
    l1.x = -fmaxf(1.f + wv[4], 0.f) * inv_spa;
    l1.y = -fmaxf(1.f + wv[5], 0.f) * inv_spa;
    l1.z = -fmaxf(1.f + wv[6], 0.f) * inv_spa;
    l1.w = -fmaxf(1.f + wv[7], 0.f) * inv_spa;
    S->bndU[rr][0][tid] = u0; S->bndU[rr][1][tid] = u1;
    S->bndL[rr][0][tid] = l0; S->bndL[rr][1][tid] = l1;
  }

  const uint32_t whx_peer   = mapa_u32(smem_u32(&S->whx[0][0]),   lane & 7);
  const uint32_t stats_peer = mapa_u32(smem_u32(&S->stats[0][0]), lane & 7);
  const uint32_t mbar_peer  = mapa_u32(mb_local,                  lane & 7);

  cluster_sync_();   // orders mbarrier init + smem state cluster-wide

  float hreg[8], tereg[8];
  {
    const float4* h4 = (const float4*)S->h;
    const float4* t4 = (const float4*)S->te;
    float4 a = h4[lane], c = h4[32 + lane];
    hreg[0]=a.x; hreg[1]=a.y; hreg[2]=a.z; hreg[3]=a.w;
    hreg[4]=c.x; hreg[5]=c.y; hreg[6]=c.z; hreg[7]=c.w;
    a = t4[lane]; c = t4[32 + lane];
    tereg[0]=a.x; tereg[1]=a.y; tereg[2]=a.z; tereg[3]=a.w;
    tereg[4]=c.x; tereg[5]=c.y; tereg[6]=c.z; tereg[7]=c.w;
  }

  float pp0 = 0.f, pp1 = 0.f;
#pragma unroll
  for (int j = 0; j < 8; ++j) { pp0 += dUr[0][j] * hreg[j]; pp1 += dUr[1][j] * hreg[j]; }

  const float4* Ws4 = (const float4*)S->Ws;
  const float4* Wm4 = (const float4*)S->Wm;

  // preloop: all 6 GEMV dots for t=0 (plastic added at loop top)
  float acc[8];
  acc[0] = dot4(Ws4[(2*wid)    * 64 + lane], hreg) + dot4(Ws4[(2*wid)    * 64 + 32 + lane], hreg + 4);
  acc[1] = dot4(Ws4[(2*wid+1)  * 64 + lane], hreg) + dot4(Ws4[(2*wid+1)  * 64 + 32 + lane], hreg + 4);
  acc[2] = dot4(Ws4[(32+2*wid) * 64 + lane], hreg) + dot4(Ws4[(32+2*wid) * 64 + 32 + lane], hreg + 4);
  acc[3] = dot4(Ws4[(33+2*wid) * 64 + lane], hreg) + dot4(Ws4[(33+2*wid) * 64 + 32 + lane], hreg + 4);
  acc[4] = dot4(Ws4[(64+2*wid) * 64 + lane], hreg) + dot4(Ws4[(64+2*wid) * 64 + 32 + lane], hreg + 4);
  acc[5] = dot4(Ws4[(65+2*wid) * 64 + lane], hreg) + dot4(Ws4[(65+2*wid) * 64 + 32 + lane], hreg + 4);

  // ================= main scan ==============================================
  int par = 0;
  for (int t = 0; t < T; ++t, par ^= 1) {
    const uint32_t use_parity = (uint32_t)(t >> 1) & 1u;
    if (iprof) cp = clock64();

    float wx0 = 0.f, wx1 = 0.f, wx2 = 0.f;
    if (tid < 256) {
      const float* wxp = &g_Wx[(size_t)(t * B + b) * H3];
      wx0 = __ldcg(wxp + tid);
      wx1 = __ldcg(wxp + tid + 256);
      wx2 = __ldcg(wxp + tid + 512);
    }

    // ---- add plastic, fold 8 -> 2, stats, exchange ----
    acc[4] += sp_a * pp0;
    acc[5] += sp_a * pp1;
    acc[6] = 0.f; acc[7] = 0.f;
#pragma unroll
    for (int k = 0; k < 4; ++k) {
      float a = (lane & 16) ? acc[k + 4] : acc[k];
      float c = (lane & 16) ? acc[k] : acc[k + 4];
      acc[k] = a + __shfl_xor_sync(~0u, c, 16);
    }
#pragma unroll
    for (int k = 0; k < 2; ++k) {
      float a = (lane & 8) ? acc[k + 2] : acc[k];
      float c = (lane & 8) ? acc[k] : acc[k + 2];
      acc[k] = a + __shfl_xor_sync(~0u, c, 8);
    }
#pragma unroll
    for (int o = 4; o; o >>= 1) {
      acc[0] += __shfl_xor_sync(~0u, acc[0], o);
      acc[1] += __shfl_xor_sync(~0u, acc[1], o);
    }
    acc[0] += pb0; acc[1] += pb1;
    float u = acc[0] + acc[1];
    float q = acc[0] * acc[0] + acc[1] * acc[1];
    u += __shfl_xor_sync(~0u, u, 8);  q += __shfl_xor_sync(~0u, q, 8);
    u += __shfl_xor_sync(~0u, u, 16); q += __shfl_xor_sync(~0u, q, 16);

    {
      const uint32_t rmbar = mbar_peer + 8u * (uint32_t)par;
      if (pgrp < 3) {
        st_async_2f(whx_peer + (uint32_t)(par * H3 + 256 * pgrp + gi0) * 4u,
                    acc[0], acc[1], rmbar);
      } else {
        st_async_2f(stats_peer + (uint32_t)(par * 128 + rank * 16 + wid) * 8u,
                    u, q, rmbar);
      }
    }
    if (iprof) { long long c = clock64(); prof[0] += (unsigned long long)(c - cp); cp = c; }

    if (wid < 8) {
      mbar_wait(mb_local + 8u * (uint32_t)par, use_parity);
      if (tid == 0) mbar_arm(mb_local + 8u * (uint32_t)par, EXPECT_BYTES);
    }
    if (iprof) { long long c = clock64(); prof[1] += (unsigned long long)(c - cp); cp = c; }

    // ---- stats combine + LN + gates ----
    if (tid < 256) {
      const float4* st4 = (const float4*)&S->stats[par][0];
      float4 A = st4[lane], Bv = st4[32 + lane];
      float su = A.x + A.z + Bv.x + Bv.z;
      float sq = A.y + A.w + Bv.y + Bv.w;
#pragma unroll
      for (int o = 16; o; o >>= 1) {
        su += __shfl_xor_sync(~0u, su, o);
        sq += __shfl_xor_sync(~0u, sq, o);
      }
      float mu   = su * (1.0f / H3);
      float var  = sq * (1.0f / H3) - mu * mu;
      float rstd = rsqrtf(var + 1e-5f);

      float w0 = S->whx[par][tid];
      float w1 = S->whx[par][256 + tid];
      float w2 = S->whx[par][512 + tid];
      float pre0 = (w0 - mu) * rstd * g0 + lb0 + wx0;
      float pre1 = (w1 - mu) * rstd * g1 + lb1 + wx1;
      float pre2 = (w2 - mu) * rstd * g2 + lb2 + wx2;
      float z  = sigm(pre0);
      float r  = sigm(pre1);
      float vn = v_own + z * (pre2 - v_own);
      float hn = fmaxf(vn, 0.f);
      float tn = te_own + r * (h_own - te_own);   // OLD h
      v_own = vn; h_own = hn; te_own = tn;
      S->h[tid]  = hn;
      S->te[tid] = tn;
      if (rank == 0) out[OUTS_OFF + (size_t)(t * B + b) * H + tid] = hn;
    }
    __syncthreads();                               // (B)
    if (iprof) { long long c = clock64(); prof[2] += (unsigned long long)(c - cp); cp = c; }

    // ---- reload column registers (new h / te) + own-row scalars ----
    float h_r0, h_r1, te_r0, te_r1;
    {
      const float4* h4 = (const float4*)S->h;
      const float4* t4 = (const float4*)S->te;
      float4 a = h4[lane], c = h4[32 + lane];
      hreg[0]=a.x; hreg[1]=a.y; hreg[2]=a.z; hreg[3]=a.w;
      hreg[4]=c.x; hreg[5]=c.y; hreg[6]=c.z; hreg[7]=c.w;
      a = t4[lane]; c = t4[32 + lane];
      tereg[0]=a.x; tereg[1]=a.y; tereg[2]=a.z; tereg[3]=a.w;
      tereg[4]=c.x; tereg[5]=c.y; tereg[6]=c.z; tereg[7]=c.w;
      h_r0 = S->h[gi0]; h_r1 = S->h[gi0 + 1];
      te_r0 = S->te[gi0]; te_r1 = S->te[gi0 + 1];
    }

    // ---- GEMV dots for NEXT step (off the mod/plastic critical chain) ----
    acc[0] = dot4(Ws4[(2*wid)    * 64 + lane], hreg) + dot4(Ws4[(2*wid)    * 64 + 32 + lane], hreg + 4);
    acc[1] = dot4(Ws4[(2*wid+1)  * 64 + lane], hreg) + dot4(Ws4[(2*wid+1)  * 64 + 32 + lane], hreg + 4);
    acc[2] = dot4(Ws4[(32+2*wid) * 64 + lane], hreg) + dot4(Ws4[(32+2*wid) * 64 + 32 + lane], hreg + 4);
    acc[3] = dot4(Ws4[(33+2*wid) * 64 + lane], hreg) + dot4(Ws4[(33+2*wid) * 64 + 32 + lane], hreg + 4);
    acc[4] = dot4(Ws4[(64+2*wid) * 64 + lane], hreg) + dot4(Ws4[(64+2*wid) * 64 + 32 + lane], hreg + 4);
    acc[5] = dot4(Ws4[(65+2*wid) * 64 + lane], hreg) + dot4(Ws4[(65+2*wid) * 64 + 32 + lane], hreg + 4);

    // ---- mod = relu(h_new @ Wm^T + b), 2 rows/warp + scalar partials ----
    {
      float m0 = dot4(Wm4[(wid * 2) * 64 + lane], hreg)
               + dot4(Wm4[(wid * 2) * 64 + 32 + lane], hreg + 4);
      float m1 = dot4(Wm4[(wid * 2 + 1) * 64 + lane], hreg)
               + dot4(Wm4[(wid * 2 + 1) * 64 + 32 + lane], hreg + 4);
      float a = (lane & 16) ? m1 : m0;
      float c = (lane & 16) ? m0 : m1;
      float vsum = a + __shfl_xor_sync(~0u, c, 16);
#pragma unroll
      for (int o = 8; o; o >>= 1) vsum += __shfl_xor_sync(~0u, vsum, o);
      float mval  = fmaxf(vsum + bhm_l, 0.f);
      float other = __shfl_xor_sync(~0u, mval, 16);
      if (lane == 0) {
        S->modred[wid] = make_float2(wsA * mval + wsB * other,
                                     wmA * mval + wmB * other);
      }
      if ((lane & 15) == 0) S->mod[mrow] = mval;
    }
    __syncthreads();                               // (C)
    if (iprof) { long long c = clock64(); prof[3] += (unsigned long long)(c - cp); cp = c; }

    // ---- s, m from modred ----
    float2 mr = S->modred[lane & 15];
    float t0 = mr.x, t1 = mr.y;
#pragma unroll
    for (int o = 8; o; o >>= 1) {
      t0 += __shfl_xor_sync(~0u, t0, o);
      t1 += __shfl_xor_sync(~0u, t1, o);
    }
    float s = sigm(t0 + bm0);
    float m = t1 + bm1;
    if (rank == 0 && tid < R)
      out[MODS_OFF + (size_t)(t * B + b) * R + tid] = S->mod[tid];

    // ---- G: dU / tE update + clip (bounds from smem) + next plastic ----
    pp0 = 0.f; pp1 = 0.f;
#pragma unroll
    for (int rr = 0; rr < 2; ++rr) {
      float hni  = (rr == 0) ? h_r0 : h_r1;
      float teni = (rr == 0) ? te_r0 : te_r1;
      float4 u0 = S->bndU[rr][0][tid], u1 = S->bndU[rr][1][tid];
      float4 l0 = S->bndL[rr][0][tid], l1 = S->bndL[rr][1][tid];
      float up[8] = {u0.x,u0.y,u0.z,u0.w,u1.x,u1.y,u1.z,u1.w};
      float lo[8] = {l0.x,l0.y,l0.z,l0.w,l1.x,l1.y,l1.z,l1.w};
      float ppl = 0.f;
#pragma unroll
      for (int j = 0; j < 8; ++j) {
        float outer = hni * tereg[j] - teni * hreg[j];
        float E = tEr[rr][j] + s * (outer - tEr[rr][j]);
        tEr[rr][j] = E;
        float d = dUr[rr][j] + tau * (m * E - dUr[rr][j]);
        d = fminf(fmaxf(d, lo[j]), up[j]);
        dUr[rr][j] = d;
        ppl += d * hreg[j];
      }
      if (rr == 0) pp0 = ppl; else pp1 = ppl;
    }
    if (iprof) { long long c = clock64(); prof[4] += (unsigned long long)(c - cp); cp = c; }
  }

  if (iprof) {
    printf("PROF fold+st=%llu wait=%llu ln=%llu dots+mod=%llu smG=%llu\n",
           prof[0], prof[1], prof[2], prof[3], prof[4]);
  }

  // ================= epilogue ===============================================
  if (rank == 0 && tid < 256) {
    out[V_OFF  + b * H + tid] = v_own;
    out[H_OFF  + b * H + tid] = h_own;
    out[TE_OFF + b * H + tid] = te_own;
  }
#pragma unroll
  for (int rr = 0; rr < 2; ++rr) {
    int gi = gi0 + rr;
    size_t rb = ((size_t)b * H + gi) * H;
    float4 a, c;
    a.x=dUr[rr][0]; a.y=dUr[rr][1]; a.z=dUr[rr][2]; a.w=dUr[rr][3];
    c.x=dUr[rr][4]; c.y=dUr[rr][5]; c.z=dUr[rr][6]; c.w=dUr[rr][7];
    ((float4*)(out + DU_OFF + rb))[lane]      = a;
    ((float4*)(out + DU_OFF + rb))[32 + lane] = c;
    a.x=tEr[rr][0]; a.y=tEr[rr][1]; a.z=tEr[rr][2]; a.w=tEr[rr][3];
    c.x=tEr[rr][4]; c.y=tEr[rr][5]; c.z=tEr[rr][6]; c.w=tEr[rr][7];
    ((float4*)(out + TEE_OFF + rb))[lane]      = a;
    ((float4*)(out + TEE_OFF + rb))[32 + lane] = c;
  }
}

extern "C" void kernel_launch(void* const* d_in, const int* in_sizes, int n_in,
                              void* d_out, int out_size) {
  (void)in_sizes; (void)n_in; (void)out_size;
  const float* x_in   = (const float*)d_in[0];
  const float* h0     = (const float*)d_in[1];
  const float* v0     = (const float*)d_in[2];
  const float* dU0    = (const float*)d_in[3];
  const float* te0    = (const float*)d_in[4];
  const float* tE0    = (const float*)d_in[5];
  const float* Wx2h   = (const float*)d_in[6];
  const float* bx2h   = (const float*)d_in[7];
  const float* Wh2h   = (const float*)d_in[8];
  const float* bh2h   = (const float*)d_in[9];
  const float* lnxg   = (const float*)d_in[10];
  const float* lnxb   = (const float*)d_in[11];
  const float* lnhg   = (const float*)d_in[12];
  const float* lnhb   = (const float*)d_in[13];
  const float* Wh2mod = (const float*)d_in[14];
  const float* bh2mod = (const float*)d_in[15];
  const float* Wmod2h = (const float*)d_in[16];
  const float* bmod2h = (const float*)d_in[17];
  const float* alpha  = (const float*)d_in[18];
  const float* tauU   = (const float*)d_in[19];
  float* out = (float*)d_out;

  cudaFuncSetAttribute(sgru_persistent,
                       cudaFuncAttributeMaxDynamicSharedMemorySize,
                       (int)sizeof(SM));
  sgru_persistent<<<B * 8, 512, sizeof(SM)>>>(
      x_in, h0, v0, dU0, te0, tE0, Wx2h, bx2h, Wh2h, bh2h,
      lnxg, lnxb, lnhg, lnhb, Wh2mod, bh2mod, Wmod2h, bmod2h,
      alpha, tauU, out);
}